// round 10
// baseline (speedup 1.0000x reference)
#include <cuda_runtime.h>
#include <cuda_bf16.h>
#include <cstdint>

// ---------------- problem constants ----------------
#define N_CB 4
#define M_CODES 512
#define D_DIM 32
#define T_POS 65536

// output layout (float32, reference tuple order, flattened+concatenated)
#define OFF_ZQ   0ULL
#define OFF_LOSS 8388608ULL
#define OFF_PERP 8388609ULL
#define OFF_IDX  8388610ULL
#define OFF_EMB  8650754ULL
#define OFF_CNT  8716290ULL
#define OFF_W    8718338ULL

// ---------------- smem layout (float offsets) ----------------
#define SXF_F   0        // fp32 x [128 pos][33]                 16896B
#define SXB_F   4224     // bf16 x packed [128][16 u32]           8192B
#define SEB_F   6272     // bf16 e packed [64 nt][128 u32]       32768B
#define SESQ_F  14464    // esq[512]
#define SXSQ_F  14976    // xsq[128]
#define SSAB_F  15104    // sum|x| [128]
#define SBEST_F 15232    // u64[128] packed (dist,code)
#define SFL_F   15488    // flag list u32[128]
#define SWS_F   15616    // warp loss partials [8]
#define SMEM_FLOATS 15624
#define SMEM_BYTES (SMEM_FLOATS * 4)   // 62496 -> 3 CTAs/SM

#define FLT_BIG 3.402823466e38f
#define MARG_COEF 3.2e-4f
#define MARG_ABS  1e-4f
#define FCAP 128

// ---------------- scratch ----------------
__device__ int    g_counts[N_CB * M_CODES];
__device__ float4 g_dw4[N_CB * M_CODES * 8];
__device__ double g_loss;

// ---------------- kernel 0: zero scratch ----------------
__global__ void vq_zero(float* __restrict__ out) {
    int i = blockIdx.x * blockDim.x + threadIdx.x;
    float* dw = (float*)g_dw4;
    if (i < N_CB * M_CODES * D_DIM) dw[i] = 0.0f;
    if (i < N_CB * M_CODES)         g_counts[i] = 0;
    if (i == 0) { g_loss = 0.0; out[OFF_PERP] = 0.0f; }
}

// ---------------- kernel 1: bf16 m16n8k16 sweep, branchless top-2, exact fp32 recheck ----------------
__global__ void __launch_bounds__(256) vq_main(const float* __restrict__ x,
                                               const float* __restrict__ emb,
                                               float* __restrict__ out) {
    extern __shared__ float sm[];
    __shared__ int fn;
    float* sXf  = sm + SXF_F;
    __nv_bfloat16* sXb = (__nv_bfloat16*)(sm + SXB_F);
    __nv_bfloat16* sEb = (__nv_bfloat16*)(sm + SEB_F);
    float* sEsq = sm + SESQ_F;
    float* sXsq = sm + SXSQ_F;
    float* sSab = sm + SSAB_F;
    unsigned long long* sBest = (unsigned long long*)(sm + SBEST_F);
    unsigned int* sFl = (unsigned int*)(sm + SFL_F);
    float* sWs  = sm + SWS_F;

    const int n    = blockIdx.y;
    const int tile = blockIdx.x;
    const int tid  = threadIdx.x;
    const int w    = tid >> 5;
    const int lane = tid & 31;
    const int g    = lane >> 2;
    const int q4   = lane & 3;

    // ---- fill x: fp32 (stride 33) + bf16 fragment-packed ----
    for (int i = tid; i < 128 * D_DIM; i += 256) {
        int d = i >> 7, p = i & 127;
        int t = tile * 128 + p;
        float v = x[(size_t)(t >> 6) * 8192 + (size_t)n * 2048 + d * 64 + (t & 63)];
        sXf[p * 33 + d] = v;
        // fragment slot: d = kt*16 + 8h + 2q + r
        int kt = d >> 4, h = (d >> 3) & 1, q = (d & 7) >> 1, r = d & 1;
        sXb[p * 32 + ((q * 4 + kt * 2 + h) << 1) + r] = __float2bfloat16(v);
    }
    // ---- fill e: bf16 fragment-packed tiles ----
    const float* en = emb + (size_t)n * M_CODES * D_DIM;
    for (int i = tid; i < M_CODES * D_DIM; i += 256) {
        int m = i >> 5, d = i & 31;
        float v = en[i];
        int nt = m >> 3, gg = m & 7;
        int kt = d >> 4, h = (d >> 3) & 1, q = (d & 7) >> 1, r = d & 1;
        sEb[nt * 256 + (((gg * 4 + q) * 4 + kt * 2 + h) << 1) + r] = __float2bfloat16(v);
    }
    if (tid == 0) fn = 0;
    __syncthreads();

    // ---- esq from gmem: ascending-d fmaf chain (reference-matching fp32) ----
    for (int c = tid; c < M_CODES; c += 256) {
        const float* er = en + c * D_DIM;
        float s = 0.0f;
#pragma unroll
        for (int d = 0; d < D_DIM; d++) s = fmaf(er[d], er[d], s);
        sEsq[c] = s;
    }
    // ---- xsq + sum|x| + sBest init ----
    if (tid < 128) {
        const float* xr = sXf + tid * 33;
        float s = 0.0f, a = 0.0f;
#pragma unroll
        for (int d = 0; d < D_DIM; d++) {
            float v = xr[d];
            s = fmaf(v, v, s);
            a += fabsf(v);
        }
        sXsq[tid] = s;
        sSab[tid] = a;
        sBest[tid] = 0xFFFFFFFFFFFFFFFFull;
    }
    __syncthreads();

    // ---- A fragments: rows r0 = w*16+g, r1 = r0+8 (one LDS.128 each) ----
    const int r0 = w * 16 + g;
    const int r1 = r0 + 8;
    const uint32_t* xb = (const uint32_t*)sXb;
    uint4 A0 = *(const uint4*)&xb[r0 * 16 + q4 * 4];   // [kt0h0, kt0h1, kt1h0, kt1h1]
    uint4 A1 = *(const uint4*)&xb[r1 * 16 + q4 * 4];

    const uint32_t* eb = (const uint32_t*)sEb;

    // ---- single branchless sweep: top-2 values + top-1 index per row ----
    float m1_0 = FLT_BIG, m2_0 = FLT_BIG, m1_1 = FLT_BIG, m2_1 = FLT_BIG;
    int   i1_0 = 0, i1_1 = 0;

#pragma unroll 4
    for (int nt = 0; nt < 64; nt++) {
        uint4 B4 = *(const uint4*)&eb[nt * 128 + lane * 4];
        float c0 = 0.0f, c1 = 0.0f, c2 = 0.0f, c3 = 0.0f;
        asm volatile(
            "mma.sync.aligned.m16n8k16.row.col.f32.bf16.bf16.f32 "
            "{%0,%1,%2,%3}, {%4,%5,%6,%7}, {%8,%9}, {%0,%1,%2,%3};"
            : "+f"(c0), "+f"(c1), "+f"(c2), "+f"(c3)
            : "r"(A0.x), "r"(A1.x), "r"(A0.y), "r"(A1.y), "r"(B4.x), "r"(B4.y));
        asm volatile(
            "mma.sync.aligned.m16n8k16.row.col.f32.bf16.bf16.f32 "
            "{%0,%1,%2,%3}, {%4,%5,%6,%7}, {%8,%9}, {%0,%1,%2,%3};"
            : "+f"(c0), "+f"(c1), "+f"(c2), "+f"(c3)
            : "r"(A0.z), "r"(A1.z), "r"(A0.w), "r"(A1.w), "r"(B4.z), "r"(B4.w));

        const int col0 = nt * 8 + q4 * 2;
        float2 e2 = *(const float2*)&sEsq[col0];
        float d00 = fmaf(c0, -2.0f, e2.x);
        float d01 = fmaf(c1, -2.0f, e2.y);
        float d10 = fmaf(c2, -2.0f, e2.x);
        float d11 = fmaf(c3, -2.0f, e2.y);

        {   // row 0: branchless top-2 + index of min
            float lo = fminf(d00, d01);
            float hi = fmaxf(d00, d01);
            int  ilo = (d01 < d00) ? (col0 + 1) : col0;
            m2_0 = fminf(m2_0, fminf(hi, fmaxf(lo, m1_0)));
            i1_0 = (lo < m1_0) ? ilo : i1_0;
            m1_0 = fminf(m1_0, lo);
        }
        {   // row 1
            float lo = fminf(d10, d11);
            float hi = fmaxf(d10, d11);
            int  ilo = (d11 < d10) ? (col0 + 1) : col0;
            m2_1 = fminf(m2_1, fminf(hi, fmaxf(lo, m1_1)));
            i1_1 = (lo < m1_1) ? ilo : i1_1;
            m1_1 = fminf(m1_1, lo);
        }
    }

    // save thread-local pre-merge state
    const float lm1_0 = m1_0, lm2_0 = m2_0, lm1_1 = m1_1, lm2_1 = m2_1;
    const int   li1_0 = i1_0, li1_1 = i1_1;

    // ---- merge across the 4 quad-threads of each row ----
#pragma unroll
    for (int o = 1; o <= 2; o <<= 1) {
        float om1 = __shfl_xor_sync(0xFFFFFFFFu, m1_0, o);
        float om2 = __shfl_xor_sync(0xFFFFFFFFu, m2_0, o);
        m2_0 = fminf(fminf(m2_0, om2), fmaxf(m1_0, om1));
        m1_0 = fminf(m1_0, om1);
        float pm1 = __shfl_xor_sync(0xFFFFFFFFu, m1_1, o);
        float pm2 = __shfl_xor_sync(0xFFFFFFFFu, m2_1, o);
        m2_1 = fminf(fminf(m2_1, pm2), fmaxf(m1_1, pm1));
        m1_1 = fminf(m1_1, pm1);
    }
    const float thr0 = m1_0 + fmaf(sSab[r0], MARG_COEF, MARG_ABS);
    const float thr1 = m1_1 + fmaf(sSab[r1], MARG_COEF, MARG_ABS);

    // ---- exact fp32 recheck (x from smem fp32, e from gmem fp32) ----
#define EXACT_CHECK(row, code) {                                                  \
        const float* xr = sXf + (row) * 33;                                       \
        const float* er = en + (code) * D_DIM;                                    \
        float dot = 0.0f;                                                         \
        _Pragma("unroll")                                                         \
        for (int d = 0; d < D_DIM; d++)                                           \
            dot = fmaf(xr[d], er[d], dot);                                        \
        float dist = fmaf(dot, -2.0f, sXsq[row] + sEsq[code]);                    \
        unsigned long long pk = ((unsigned long long)__float_as_uint(dist) << 32) \
                                | (unsigned int)(code);                           \
        atomicMin(&sBest[row], pk);                                               \
    }

    if (lm1_0 <= thr0) EXACT_CHECK(r0, li1_0)
    if (lm1_1 <= thr1) EXACT_CHECK(r1, li1_1)
    if (lm2_0 <= thr0) { int s = atomicAdd(&fn, 1); if (s < FCAP) sFl[s] = (r0 << 2) | q4; }
    if (lm2_1 <= thr1) { int s = atomicAdd(&fn, 1); if (s < FCAP) sFl[s] = (r1 << 2) | q4; }
    __syncthreads();

    // ---- cooperative exact rescan of flagged (row, quad) 128-code ranges ----
    {
        const int nf = (fn < FCAP) ? fn : FCAP;
        for (int i = tid; i < nf * 128; i += 256) {
            const int e = i >> 7, k = i & 127;
            const unsigned int fl = sFl[e];
            const int row = fl >> 2, q = fl & 3;
            const int code = (k >> 1) * 8 + q * 2 + (k & 1);
            EXACT_CHECK(row, code)
        }
        if (fn > FCAP) {   // overflow fallback (practically never)
            for (int i = tid; i < 128 * M_CODES; i += 256) {
                EXACT_CHECK(i >> 9, i & 511)
            }
        }
    }
#undef EXACT_CHECK
    __syncthreads();

    // ---- epilogue: outputs per position ----
    float lloss = 0.0f;
    if (tid < 128) {
        const int pp = tid;
        const int bi = (int)(sBest[pp] & 0xFFFFFFFFull);

        const int t = tile * 128 + pp;
        const int b = t >> 6, l = t & 63;
        out[OFF_IDX + (size_t)b * 256 + (size_t)n * 64 + l] = (float)bi;
        atomicAdd(&g_counts[n * M_CODES + bi], 1);

        float4* dwp = g_dw4 + ((size_t)n * M_CODES + bi) * 8;
        float*  zq  = out + OFF_ZQ + (size_t)b * 8192 + (size_t)n * 2048 + l;
        const float* xr = sXf + pp * 33;
        const float* er = en + bi * D_DIM;
#pragma unroll
        for (int d4 = 0; d4 < 8; d4++) {
            float xv0 = xr[d4 * 4 + 0], q0 = er[d4 * 4 + 0];
            float xv1 = xr[d4 * 4 + 1], q1 = er[d4 * 4 + 1];
            float xv2 = xr[d4 * 4 + 2], q2 = er[d4 * 4 + 2];
            float xv3 = xr[d4 * 4 + 3], q3 = er[d4 * 4 + 3];
            zq[(d4 * 4 + 0) * 64] = __fsub_rn(__fadd_rn(q0, xv0), xv0);
            zq[(d4 * 4 + 1) * 64] = __fsub_rn(__fadd_rn(q1, xv1), xv1);
            zq[(d4 * 4 + 2) * 64] = __fsub_rn(__fadd_rn(q2, xv2), xv2);
            zq[(d4 * 4 + 3) * 64] = __fsub_rn(__fadd_rn(q3, xv3), xv3);
            float f0 = xv0 - q0, f1 = xv1 - q1, f2 = xv2 - q2, f3 = xv3 - q3;
            lloss = fmaf(f0, f0, lloss);
            lloss = fmaf(f1, f1, lloss);
            lloss = fmaf(f2, f2, lloss);
            lloss = fmaf(f3, f3, lloss);
            atomicAdd(dwp + d4, make_float4(xv0, xv1, xv2, xv3));
        }
    }

    // ---- CTA loss reduction -> one double atomic ----
#pragma unroll
    for (int o = 16; o > 0; o >>= 1) lloss += __shfl_down_sync(0xFFFFFFFFu, lloss, o);
    if (lane == 0) sWs[w] = lloss;
    __syncthreads();
    if (tid == 0) {
        double s = 0.0;
#pragma unroll
        for (int ww = 0; ww < 8; ww++) s += (double)sWs[ww];
        atomicAdd(&g_loss, s);
    }
}

// ---------------- kernel 2: EMA / Laplace / embedding / perplexity / loss ----------------
__global__ void vq_fin(const float* __restrict__ ema_c,
                       const float* __restrict__ ema_w,
                       float* __restrict__ out) {
    const int n = blockIdx.x;
    const int m = threadIdx.x;
    __shared__ float red[M_CODES];
    const float* g_dwf = (const float*)g_dw4;

    const float DECAY = 0.999f;
    const float OMD   = (float)(1.0 - 0.999);
    const float MEPS  = (float)(512.0 * 1e-5);

    float cnt  = (float)g_counts[n * M_CODES + m];
    float cnew = DECAY * ema_c[n * M_CODES + m] + OMD * cnt;

    red[m] = cnew;
    __syncthreads();
    for (int s = 256; s > 0; s >>= 1) {
        if (m < s) red[m] += red[m + s];
        __syncthreads();
    }
    float ntot = red[0];
    __syncthreads();

    float clap = (cnew + 1e-5f) / (ntot + MEPS) * ntot;
    out[OFF_CNT + (size_t)n * M_CODES + m] = clap;

#pragma unroll
    for (int d = 0; d < D_DIM; d++) {
        size_t idx = ((size_t)n * M_CODES + m) * D_DIM + d;
        float wv = DECAY * ema_w[idx] + OMD * g_dwf[idx];
        out[OFF_W + idx]   = wv;
        out[OFF_EMB + idx] = wv / clap;
    }

    float p    = cnt * (1.0f / 65536.0f);
    float term = p * logf(p + 1e-10f);
    red[m] = term;
    __syncthreads();
    for (int s = 256; s > 0; s >>= 1) {
        if (m < s) red[m] += red[m + s];
        __syncthreads();
    }
    if (m == 0) {
        atomicAdd(&out[OFF_PERP], expf(-red[0]));
        if (n == 0) out[OFF_LOSS] = (float)(0.25 * g_loss * (1.0 / 8388608.0));
    }
}

// ---------------- launch ----------------
extern "C" void kernel_launch(void* const* d_in, const int* in_sizes, int n_in,
                              void* d_out, int out_size) {
    const float* x     = (const float*)d_in[0];
    const float* emb   = (const float*)d_in[1];
    const float* ema_c = (const float*)d_in[2];
    const float* ema_w = (const float*)d_in[3];
    float* out = (float*)d_out;

    cudaFuncSetAttribute(vq_main, cudaFuncAttributeMaxDynamicSharedMemorySize, SMEM_BYTES);

    vq_zero<<<256, 256>>>(out);
    vq_main<<<dim3(T_POS / 128, N_CB), 256, SMEM_BYTES>>>(x, emb, out);
    vq_fin<<<N_CB, M_CODES>>>(ema_c, ema_w, out);
}

// round 11
// speedup vs baseline: 2.0485x; 2.0485x over previous
#include <cuda_runtime.h>
#include <cuda_bf16.h>
#include <cstdint>

// ---------------- problem constants ----------------
#define N_CB 4
#define M_CODES 512
#define D_DIM 32
#define T_POS 65536

// output layout (float32, reference tuple order, flattened+concatenated)
#define OFF_ZQ   0ULL
#define OFF_LOSS 8388608ULL
#define OFF_PERP 8388609ULL
#define OFF_IDX  8388610ULL
#define OFF_EMB  8650754ULL
#define OFF_CNT  8716290ULL
#define OFF_W    8718338ULL

// ---------------- smem layout (float offsets) ----------------
#define SXF_F   0        // fp32 x [128 pos][33]                16896B
#define SXB_F   4224     // bf16 x_hi packed [128][16 u32]       8192B
#define SXL_F   6272     // bf16 x_lo packed [128][16 u32]       8192B
#define SEB_F   8320     // bf16 e_hi packed [64 nt][128 u32]   32768B
#define SESQ_F  16512    // esq[512]
#define SXSQ_F  17024    // xsq[128]
#define SSAB_F  17152    // sum|x| [128]
#define SBEST_F 17280    // u64[128] packed (dist,code)
#define SFL_F   17536    // flag list u32[256]
#define SWS_F   17792    // warp loss partials [8]
#define SMEM_FLOATS 17800
#define SMEM_BYTES (SMEM_FLOATS * 4)   // 71200 -> 3 CTAs/SM

#define FLT_BIG 3.402823466e38f
// split-bf16 residual: only e-rounding survives -> Sab*max|e|*2^-9*2 ~ Sab*3.8e-5
#define MARG_COEF 8e-5f
#define MARG_ABS  5e-5f
#define FCAP 256

// ---------------- scratch ----------------
__device__ int    g_counts[N_CB * M_CODES];
__device__ float4 g_dw4[N_CB * M_CODES * 8];
__device__ double g_loss;

// ---------------- kernel 0: zero scratch ----------------
__global__ void vq_zero(float* __restrict__ out) {
    int i = blockIdx.x * blockDim.x + threadIdx.x;
    float* dw = (float*)g_dw4;
    if (i < N_CB * M_CODES * D_DIM) dw[i] = 0.0f;
    if (i < N_CB * M_CODES)         g_counts[i] = 0;
    if (i == 0) { g_loss = 0.0; out[OFF_PERP] = 0.0f; }
}

// ---------------- kernel 1: split-bf16 m16n8k16 sweep, branchless top-2, exact fp32 recheck ----------------
__global__ void __launch_bounds__(256) vq_main(const float* __restrict__ x,
                                               const float* __restrict__ emb,
                                               float* __restrict__ out) {
    extern __shared__ float sm[];
    __shared__ int fn;
    float* sXf  = sm + SXF_F;
    __nv_bfloat16* sXb = (__nv_bfloat16*)(sm + SXB_F);
    __nv_bfloat16* sXl = (__nv_bfloat16*)(sm + SXL_F);
    __nv_bfloat16* sEb = (__nv_bfloat16*)(sm + SEB_F);
    float* sEsq = sm + SESQ_F;
    float* sXsq = sm + SXSQ_F;
    float* sSab = sm + SSAB_F;
    unsigned long long* sBest = (unsigned long long*)(sm + SBEST_F);
    unsigned int* sFl = (unsigned int*)(sm + SFL_F);
    float* sWs  = sm + SWS_F;

    const int n    = blockIdx.y;
    const int tile = blockIdx.x;
    const int tid  = threadIdx.x;
    const int w    = tid >> 5;
    const int lane = tid & 31;
    const int g    = lane >> 2;
    const int q4   = lane & 3;

    // ---- fill x: fp32 (stride 33) + split-bf16 fragment-packed ----
    for (int i = tid; i < 128 * D_DIM; i += 256) {
        int d = i >> 7, p = i & 127;
        int t = tile * 128 + p;
        float v = x[(size_t)(t >> 6) * 8192 + (size_t)n * 2048 + d * 64 + (t & 63)];
        sXf[p * 33 + d] = v;
        __nv_bfloat16 vh = __float2bfloat16(v);
        __nv_bfloat16 vl = __float2bfloat16(v - __bfloat162float(vh));
        int kt = d >> 4, h = (d >> 3) & 1, q = (d & 7) >> 1, r = d & 1;
        int slot = ((q * 4 + kt * 2 + h) << 1) + r;
        sXb[p * 32 + slot] = vh;
        sXl[p * 32 + slot] = vl;
    }
    // ---- fill e: bf16 fragment-packed tiles ----
    const float* en = emb + (size_t)n * M_CODES * D_DIM;
    for (int i = tid; i < M_CODES * D_DIM; i += 256) {
        int m = i >> 5, d = i & 31;
        float v = en[i];
        int nt = m >> 3, gg = m & 7;
        int kt = d >> 4, h = (d >> 3) & 1, q = (d & 7) >> 1, r = d & 1;
        sEb[nt * 256 + (((gg * 4 + q) * 4 + kt * 2 + h) << 1) + r] = __float2bfloat16(v);
    }
    if (tid == 0) fn = 0;
    __syncthreads();

    // ---- esq from gmem: ascending-d fmaf chain (reference-matching fp32) ----
    for (int c = tid; c < M_CODES; c += 256) {
        const float* er = en + c * D_DIM;
        float s = 0.0f;
#pragma unroll
        for (int d = 0; d < D_DIM; d++) s = fmaf(er[d], er[d], s);
        sEsq[c] = s;
    }
    // ---- xsq + sum|x| + sBest init ----
    if (tid < 128) {
        const float* xr = sXf + tid * 33;
        float s = 0.0f, a = 0.0f;
#pragma unroll
        for (int d = 0; d < D_DIM; d++) {
            float v = xr[d];
            s = fmaf(v, v, s);
            a += fabsf(v);
        }
        sXsq[tid] = s;
        sSab[tid] = a;
        sBest[tid] = 0xFFFFFFFFFFFFFFFFull;
    }
    __syncthreads();

    // ---- A fragments: rows r0 = w*16+g, r1 = r0+8 ----
    const int r0 = w * 16 + g;
    const int r1 = r0 + 8;
    const uint32_t* xb = (const uint32_t*)sXb;
    const uint32_t* xl = (const uint32_t*)sXl;
    uint4 A0 = *(const uint4*)&xb[r0 * 16 + q4 * 4];   // [kt0h0, kt0h1, kt1h0, kt1h1]
    uint4 A1 = *(const uint4*)&xb[r1 * 16 + q4 * 4];
    uint4 L0 = *(const uint4*)&xl[r0 * 16 + q4 * 4];
    uint4 L1 = *(const uint4*)&xl[r1 * 16 + q4 * 4];

    const uint32_t* eb = (const uint32_t*)sEb;

    // ---- single branchless sweep: top-2 values + top-1 index per row ----
    float m1_0 = FLT_BIG, m2_0 = FLT_BIG, m1_1 = FLT_BIG, m2_1 = FLT_BIG;
    int   i1_0 = 0, i1_1 = 0;

#pragma unroll 4
    for (int nt = 0; nt < 64; nt++) {
        uint4 B4 = *(const uint4*)&eb[nt * 128 + lane * 4];
        float c0 = 0.0f, c1 = 0.0f, c2 = 0.0f, c3 = 0.0f;
        asm volatile(
            "mma.sync.aligned.m16n8k16.row.col.f32.bf16.bf16.f32 "
            "{%0,%1,%2,%3}, {%4,%5,%6,%7}, {%8,%9}, {%0,%1,%2,%3};"
            : "+f"(c0), "+f"(c1), "+f"(c2), "+f"(c3)
            : "r"(A0.x), "r"(A1.x), "r"(A0.y), "r"(A1.y), "r"(B4.x), "r"(B4.y));
        asm volatile(
            "mma.sync.aligned.m16n8k16.row.col.f32.bf16.bf16.f32 "
            "{%0,%1,%2,%3}, {%4,%5,%6,%7}, {%8,%9}, {%0,%1,%2,%3};"
            : "+f"(c0), "+f"(c1), "+f"(c2), "+f"(c3)
            : "r"(A0.z), "r"(A1.z), "r"(A0.w), "r"(A1.w), "r"(B4.z), "r"(B4.w));
        asm volatile(
            "mma.sync.aligned.m16n8k16.row.col.f32.bf16.bf16.f32 "
            "{%0,%1,%2,%3}, {%4,%5,%6,%7}, {%8,%9}, {%0,%1,%2,%3};"
            : "+f"(c0), "+f"(c1), "+f"(c2), "+f"(c3)
            : "r"(L0.x), "r"(L1.x), "r"(L0.y), "r"(L1.y), "r"(B4.x), "r"(B4.y));
        asm volatile(
            "mma.sync.aligned.m16n8k16.row.col.f32.bf16.bf16.f32 "
            "{%0,%1,%2,%3}, {%4,%5,%6,%7}, {%8,%9}, {%0,%1,%2,%3};"
            : "+f"(c0), "+f"(c1), "+f"(c2), "+f"(c3)
            : "r"(L0.z), "r"(L1.z), "r"(L0.w), "r"(L1.w), "r"(B4.z), "r"(B4.w));

        const int col0 = nt * 8 + q4 * 2;
        float2 e2 = *(const float2*)&sEsq[col0];
        float d00 = fmaf(c0, -2.0f, e2.x);
        float d01 = fmaf(c1, -2.0f, e2.y);
        float d10 = fmaf(c2, -2.0f, e2.x);
        float d11 = fmaf(c3, -2.0f, e2.y);

        {   // row 0: branchless top-2 + index of min
            float lo = fminf(d00, d01);
            float hi = fmaxf(d00, d01);
            int  ilo = (d01 < d00) ? (col0 + 1) : col0;
            m2_0 = fminf(m2_0, fminf(hi, fmaxf(lo, m1_0)));
            i1_0 = (lo < m1_0) ? ilo : i1_0;
            m1_0 = fminf(m1_0, lo);
        }
        {   // row 1
            float lo = fminf(d10, d11);
            float hi = fmaxf(d10, d11);
            int  ilo = (d11 < d10) ? (col0 + 1) : col0;
            m2_1 = fminf(m2_1, fminf(hi, fmaxf(lo, m1_1)));
            i1_1 = (lo < m1_1) ? ilo : i1_1;
            m1_1 = fminf(m1_1, lo);
        }
    }

    // save thread-local pre-merge state
    const float lm1_0 = m1_0, lm2_0 = m2_0, lm1_1 = m1_1, lm2_1 = m2_1;
    const int   li1_0 = i1_0, li1_1 = i1_1;

    // ---- merge across the 4 quad-threads of each row ----
#pragma unroll
    for (int o = 1; o <= 2; o <<= 1) {
        float om1 = __shfl_xor_sync(0xFFFFFFFFu, m1_0, o);
        float om2 = __shfl_xor_sync(0xFFFFFFFFu, m2_0, o);
        m2_0 = fminf(fminf(m2_0, om2), fmaxf(m1_0, om1));
        m1_0 = fminf(m1_0, om1);
        float pm1 = __shfl_xor_sync(0xFFFFFFFFu, m1_1, o);
        float pm2 = __shfl_xor_sync(0xFFFFFFFFu, m2_1, o);
        m2_1 = fminf(fminf(m2_1, pm2), fmaxf(m1_1, pm1));
        m1_1 = fminf(m1_1, pm1);
    }
    const float thr0 = m1_0 + fmaf(sSab[r0], MARG_COEF, MARG_ABS);
    const float thr1 = m1_1 + fmaf(sSab[r1], MARG_COEF, MARG_ABS);

    // ---- exact fp32 recheck (x from smem fp32, e from gmem fp32) ----
#define EXACT_CHECK(row, code) {                                                  \
        const float* xr = sXf + (row) * 33;                                       \
        const float* er = en + (code) * D_DIM;                                    \
        float dot = 0.0f;                                                         \
        _Pragma("unroll")                                                         \
        for (int d = 0; d < D_DIM; d++)                                           \
            dot = fmaf(xr[d], er[d], dot);                                        \
        float dist = fmaf(dot, -2.0f, sXsq[row] + sEsq[code]);                    \
        unsigned long long pk = ((unsigned long long)__float_as_uint(dist) << 32) \
                                | (unsigned int)(code);                           \
        atomicMin(&sBest[row], pk);                                               \
    }

    if (lm1_0 <= thr0) EXACT_CHECK(r0, li1_0)
    if (lm1_1 <= thr1) EXACT_CHECK(r1, li1_1)
    if (lm2_0 <= thr0) { int s = atomicAdd(&fn, 1); if (s < FCAP) sFl[s] = (r0 << 2) | q4; }
    if (lm2_1 <= thr1) { int s = atomicAdd(&fn, 1); if (s < FCAP) sFl[s] = (r1 << 2) | q4; }
    __syncthreads();

    // ---- cooperative exact rescan of flagged (row, quad) 128-code ranges ----
    {
        const int nf = (fn < FCAP) ? fn : FCAP;
        for (int i = tid; i < nf * 128; i += 256) {
            const int e = i >> 7, k = i & 127;
            const unsigned int fl = sFl[e];
            const int row = fl >> 2, q = fl & 3;
            const int code = (k >> 1) * 8 + q * 2 + (k & 1);
            EXACT_CHECK(row, code)
        }
        if (fn > FCAP) {   // overflow fallback (margin math says never)
            for (int i = tid; i < 128 * M_CODES; i += 256) {
                EXACT_CHECK(i >> 9, i & 511)
            }
        }
    }
#undef EXACT_CHECK
    __syncthreads();

    // ---- epilogue: outputs per position ----
    float lloss = 0.0f;
    if (tid < 128) {
        const int pp = tid;
        const int bi = (int)(sBest[pp] & 0xFFFFFFFFull);

        const int t = tile * 128 + pp;
        const int b = t >> 6, l = t & 63;
        out[OFF_IDX + (size_t)b * 256 + (size_t)n * 64 + l] = (float)bi;
        atomicAdd(&g_counts[n * M_CODES + bi], 1);

        float4* dwp = g_dw4 + ((size_t)n * M_CODES + bi) * 8;
        float*  zq  = out + OFF_ZQ + (size_t)b * 8192 + (size_t)n * 2048 + l;
        const float* xr = sXf + pp * 33;
        const float* er = en + bi * D_DIM;
#pragma unroll
        for (int d4 = 0; d4 < 8; d4++) {
            float xv0 = xr[d4 * 4 + 0], q0 = er[d4 * 4 + 0];
            float xv1 = xr[d4 * 4 + 1], q1 = er[d4 * 4 + 1];
            float xv2 = xr[d4 * 4 + 2], q2 = er[d4 * 4 + 2];
            float xv3 = xr[d4 * 4 + 3], q3 = er[d4 * 4 + 3];
            zq[(d4 * 4 + 0) * 64] = __fsub_rn(__fadd_rn(q0, xv0), xv0);
            zq[(d4 * 4 + 1) * 64] = __fsub_rn(__fadd_rn(q1, xv1), xv1);
            zq[(d4 * 4 + 2) * 64] = __fsub_rn(__fadd_rn(q2, xv2), xv2);
            zq[(d4 * 4 + 3) * 64] = __fsub_rn(__fadd_rn(q3, xv3), xv3);
            float f0 = xv0 - q0, f1 = xv1 - q1, f2 = xv2 - q2, f3 = xv3 - q3;
            lloss = fmaf(f0, f0, lloss);
            lloss = fmaf(f1, f1, lloss);
            lloss = fmaf(f2, f2, lloss);
            lloss = fmaf(f3, f3, lloss);
            atomicAdd(dwp + d4, make_float4(xv0, xv1, xv2, xv3));
        }
    }

    // ---- CTA loss reduction -> one double atomic ----
#pragma unroll
    for (int o = 16; o > 0; o >>= 1) lloss += __shfl_down_sync(0xFFFFFFFFu, lloss, o);
    if (lane == 0) sWs[w] = lloss;
    __syncthreads();
    if (tid == 0) {
        double s = 0.0;
#pragma unroll
        for (int ww = 0; ww < 8; ww++) s += (double)sWs[ww];
        atomicAdd(&g_loss, s);
    }
}

// ---------------- kernel 2: EMA / Laplace / embedding / perplexity / loss ----------------
__global__ void vq_fin(const float* __restrict__ ema_c,
                       const float* __restrict__ ema_w,
                       float* __restrict__ out) {
    const int n = blockIdx.x;
    const int m = threadIdx.x;
    __shared__ float red[M_CODES];
    const float* g_dwf = (const float*)g_dw4;

    const float DECAY = 0.999f;
    const float OMD   = (float)(1.0 - 0.999);
    const float MEPS  = (float)(512.0 * 1e-5);

    float cnt  = (float)g_counts[n * M_CODES + m];
    float cnew = DECAY * ema_c[n * M_CODES + m] + OMD * cnt;

    red[m] = cnew;
    __syncthreads();
    for (int s = 256; s > 0; s >>= 1) {
        if (m < s) red[m] += red[m + s];
        __syncthreads();
    }
    float ntot = red[0];
    __syncthreads();

    float clap = (cnew + 1e-5f) / (ntot + MEPS) * ntot;
    out[OFF_CNT + (size_t)n * M_CODES + m] = clap;

#pragma unroll
    for (int d = 0; d < D_DIM; d++) {
        size_t idx = ((size_t)n * M_CODES + m) * D_DIM + d;
        float wv = DECAY * ema_w[idx] + OMD * g_dwf[idx];
        out[OFF_W + idx]   = wv;
        out[OFF_EMB + idx] = wv / clap;
    }

    float p    = cnt * (1.0f / 65536.0f);
    float term = p * logf(p + 1e-10f);
    red[m] = term;
    __syncthreads();
    for (int s = 256; s > 0; s >>= 1) {
        if (m < s) red[m] += red[m + s];
        __syncthreads();
    }
    if (m == 0) {
        atomicAdd(&out[OFF_PERP], expf(-red[0]));
        if (n == 0) out[OFF_LOSS] = (float)(0.25 * g_loss * (1.0 / 8388608.0));
    }
}

// ---------------- launch ----------------
extern "C" void kernel_launch(void* const* d_in, const int* in_sizes, int n_in,
                              void* d_out, int out_size) {
    const float* x     = (const float*)d_in[0];
    const float* emb   = (const float*)d_in[1];
    const float* ema_c = (const float*)d_in[2];
    const float* ema_w = (const float*)d_in[3];
    float* out = (float*)d_out;

    cudaFuncSetAttribute(vq_main, cudaFuncAttributeMaxDynamicSharedMemorySize, SMEM_BYTES);

    vq_zero<<<256, 256>>>(out);
    vq_main<<<dim3(T_POS / 128, N_CB), 256, SMEM_BYTES>>>(x, emb, out);
    vq_fin<<<N_CB, M_CODES>>>(ema_c, ema_w, out);
}

// round 12
// speedup vs baseline: 4.0175x; 1.9612x over previous
#include <cuda_runtime.h>
#include <cuda_bf16.h>
#include <cstdint>

// ---------------- problem constants ----------------
#define N_CB 4
#define M_CODES 512
#define D_DIM 32
#define T_POS 65536

// output layout (float32, reference tuple order, flattened+concatenated)
#define OFF_ZQ   0ULL
#define OFF_LOSS 8388608ULL
#define OFF_PERP 8388609ULL
#define OFF_IDX  8388610ULL
#define OFF_EMB  8650754ULL
#define OFF_CNT  8716290ULL
#define OFF_W    8718338ULL

// ---------------- smem layout (float offsets) ----------------
#define SXF_F   0        // fp32 x [128 pos][36]                18432B
#define SXB_F   4608     // bf16 x_hi packed [128][16 u32]       8192B
#define SXL_F   6656     // bf16 x_lo packed [128][16 u32]       8192B
#define SEB_F   8704     // bf16 e_hi packed [64 nt][128 u32]   32768B
#define SESQ_F  16896    // esq[512]
#define SXSQ_F  17408    // xsq[128]
#define SSAB_F  17536    // sum|x| [128]
#define SBEST_F 17664    // u64[128] packed (dist,code)
#define SQ1_F   17920    // singles queue u32[512]
#define SFL_F   18432    // range-flag queue u32[256]
#define SWS_F   18688    // warp loss partials [8]
#define SMEM_FLOATS 18696
#define SMEM_BYTES (SMEM_FLOATS * 4)   // 74784 -> 3 CTAs/SM

#define FLT_BIG 3.402823466e38f
// split-bf16 residual: only e-rounding survives -> 2*Sab*max|e|*2^-9 ~ Sab*3.8e-5
#define MARG_COEF 1e-4f
#define MARG_ABS  5e-5f
#define Q1CAP 512
#define FCAP  256

// ---------------- scratch ----------------
__device__ int    g_counts[N_CB * M_CODES];
__device__ float4 g_dw4[N_CB * M_CODES * 8];
__device__ double g_loss;

// ---------------- kernel 0: zero scratch ----------------
__global__ void vq_zero(float* __restrict__ out) {
    int i = blockIdx.x * blockDim.x + threadIdx.x;
    float* dw = (float*)g_dw4;
    if (i < N_CB * M_CODES * D_DIM) dw[i] = 0.0f;
    if (i < N_CB * M_CODES)         g_counts[i] = 0;
    if (i == 0) { g_loss = 0.0; out[OFF_PERP] = 0.0f; }
}

// ---------------- kernel 1: split-bf16 sweep + coalesced warp-cooperative recheck ----------------
__global__ void __launch_bounds__(256) vq_main(const float* __restrict__ x,
                                               const float* __restrict__ emb,
                                               float* __restrict__ out) {
    extern __shared__ float sm[];
    __shared__ int qn1, fn;
    float* sXf  = sm + SXF_F;
    __nv_bfloat16* sXb = (__nv_bfloat16*)(sm + SXB_F);
    __nv_bfloat16* sXl = (__nv_bfloat16*)(sm + SXL_F);
    __nv_bfloat16* sEb = (__nv_bfloat16*)(sm + SEB_F);
    float* sEsq = sm + SESQ_F;
    float* sXsq = sm + SXSQ_F;
    float* sSab = sm + SSAB_F;
    unsigned long long* sBest = (unsigned long long*)(sm + SBEST_F);
    unsigned int* sQ1 = (unsigned int*)(sm + SQ1_F);
    unsigned int* sFl = (unsigned int*)(sm + SFL_F);
    float* sWs  = sm + SWS_F;

    const int n    = blockIdx.y;
    const int tile = blockIdx.x;
    const int tid  = threadIdx.x;
    const int w    = tid >> 5;
    const int lane = tid & 31;
    const int g    = lane >> 2;
    const int q4   = lane & 3;

    // ---- fill x: fp32 (stride 36) + split-bf16 fragment-packed ----
    for (int i = tid; i < 128 * D_DIM; i += 256) {
        int d = i >> 7, p = i & 127;
        int t = tile * 128 + p;
        float v = x[(size_t)(t >> 6) * 8192 + (size_t)n * 2048 + d * 64 + (t & 63)];
        sXf[p * 36 + d] = v;
        __nv_bfloat16 vh = __float2bfloat16(v);
        __nv_bfloat16 vl = __float2bfloat16(v - __bfloat162float(vh));
        int kt = d >> 4, h = (d >> 3) & 1, q = (d & 7) >> 1, r = d & 1;
        int slot = ((q * 4 + kt * 2 + h) << 1) + r;
        sXb[p * 32 + slot] = vh;
        sXl[p * 32 + slot] = vl;
    }
    // ---- fill e: bf16 fragment-packed tiles ----
    const float* en = emb + (size_t)n * M_CODES * D_DIM;
    for (int i = tid; i < M_CODES * D_DIM; i += 256) {
        int m = i >> 5, d = i & 31;
        float v = en[i];
        int nt = m >> 3, gg = m & 7;
        int kt = d >> 4, h = (d >> 3) & 1, q = (d & 7) >> 1, r = d & 1;
        sEb[nt * 256 + (((gg * 4 + q) * 4 + kt * 2 + h) << 1) + r] = __float2bfloat16(v);
    }
    if (tid == 0) { qn1 = 0; fn = 0; }

    // ---- esq: coalesced 8-lanes-per-code (warp w handles codes [64w, 64w+64)) ----
    for (int it = 0; it < 16; it++) {
        int code = w * 64 + it * 4 + (lane >> 3);
        int d4 = lane & 7;
        float4 ev = *(const float4*)(en + code * 32 + d4 * 4);
        float p = ev.x * ev.x;
        p = fmaf(ev.y, ev.y, p);
        p = fmaf(ev.z, ev.z, p);
        p = fmaf(ev.w, ev.w, p);
        p += __shfl_xor_sync(0xFFFFFFFFu, p, 1);
        p += __shfl_xor_sync(0xFFFFFFFFu, p, 2);
        p += __shfl_xor_sync(0xFFFFFFFFu, p, 4);
        if (d4 == 0) sEsq[code] = p;
    }
    __syncthreads();

    // ---- xsq + sum|x| + sBest init ----
    if (tid < 128) {
        const float* xr = sXf + tid * 36;
        float s = 0.0f, a = 0.0f;
#pragma unroll
        for (int d = 0; d < D_DIM; d++) {
            float v = xr[d];
            s = fmaf(v, v, s);
            a += fabsf(v);
        }
        sXsq[tid] = s;
        sSab[tid] = a;
        sBest[tid] = 0xFFFFFFFFFFFFFFFFull;
    }
    __syncthreads();

    // ---- A fragments ----
    const int r0 = w * 16 + g;
    const int r1 = r0 + 8;
    const uint32_t* xb = (const uint32_t*)sXb;
    const uint32_t* xl = (const uint32_t*)sXl;
    uint4 A0 = *(const uint4*)&xb[r0 * 16 + q4 * 4];
    uint4 A1 = *(const uint4*)&xb[r1 * 16 + q4 * 4];
    uint4 L0 = *(const uint4*)&xl[r0 * 16 + q4 * 4];
    uint4 L1 = *(const uint4*)&xl[r1 * 16 + q4 * 4];

    const uint32_t* eb = (const uint32_t*)sEb;

    // ---- single branchless sweep: top-2 values + top-1 index per row ----
    float m1_0 = FLT_BIG, m2_0 = FLT_BIG, m1_1 = FLT_BIG, m2_1 = FLT_BIG;
    int   i1_0 = 0, i1_1 = 0;

#pragma unroll 4
    for (int nt = 0; nt < 64; nt++) {
        uint4 B4 = *(const uint4*)&eb[nt * 128 + lane * 4];
        float c0 = 0.0f, c1 = 0.0f, c2 = 0.0f, c3 = 0.0f;
        asm volatile(
            "mma.sync.aligned.m16n8k16.row.col.f32.bf16.bf16.f32 "
            "{%0,%1,%2,%3}, {%4,%5,%6,%7}, {%8,%9}, {%0,%1,%2,%3};"
            : "+f"(c0), "+f"(c1), "+f"(c2), "+f"(c3)
            : "r"(A0.x), "r"(A1.x), "r"(A0.y), "r"(A1.y), "r"(B4.x), "r"(B4.y));
        asm volatile(
            "mma.sync.aligned.m16n8k16.row.col.f32.bf16.bf16.f32 "
            "{%0,%1,%2,%3}, {%4,%5,%6,%7}, {%8,%9}, {%0,%1,%2,%3};"
            : "+f"(c0), "+f"(c1), "+f"(c2), "+f"(c3)
            : "r"(A0.z), "r"(A1.z), "r"(A0.w), "r"(A1.w), "r"(B4.z), "r"(B4.w));
        asm volatile(
            "mma.sync.aligned.m16n8k16.row.col.f32.bf16.bf16.f32 "
            "{%0,%1,%2,%3}, {%4,%5,%6,%7}, {%8,%9}, {%0,%1,%2,%3};"
            : "+f"(c0), "+f"(c1), "+f"(c2), "+f"(c3)
            : "r"(L0.x), "r"(L1.x), "r"(L0.y), "r"(L1.y), "r"(B4.x), "r"(B4.y));
        asm volatile(
            "mma.sync.aligned.m16n8k16.row.col.f32.bf16.bf16.f32 "
            "{%0,%1,%2,%3}, {%4,%5,%6,%7}, {%8,%9}, {%0,%1,%2,%3};"
            : "+f"(c0), "+f"(c1), "+f"(c2), "+f"(c3)
            : "r"(L0.z), "r"(L1.z), "r"(L0.w), "r"(L1.w), "r"(B4.z), "r"(B4.w));

        const int col0 = nt * 8 + q4 * 2;
        float2 e2 = *(const float2*)&sEsq[col0];
        float d00 = fmaf(c0, -2.0f, e2.x);
        float d01 = fmaf(c1, -2.0f, e2.y);
        float d10 = fmaf(c2, -2.0f, e2.x);
        float d11 = fmaf(c3, -2.0f, e2.y);

        {   // row 0: branchless top-2 + index of min
            float lo = fminf(d00, d01);
            float hi = fmaxf(d00, d01);
            int  ilo = (d01 < d00) ? (col0 + 1) : col0;
            m2_0 = fminf(m2_0, fminf(hi, fmaxf(lo, m1_0)));
            i1_0 = (lo < m1_0) ? ilo : i1_0;
            m1_0 = fminf(m1_0, lo);
        }
        {   // row 1
            float lo = fminf(d10, d11);
            float hi = fmaxf(d10, d11);
            int  ilo = (d11 < d10) ? (col0 + 1) : col0;
            m2_1 = fminf(m2_1, fminf(hi, fmaxf(lo, m1_1)));
            i1_1 = (lo < m1_1) ? ilo : i1_1;
            m1_1 = fminf(m1_1, lo);
        }
    }

    // save thread-local pre-merge state
    const float lm1_0 = m1_0, lm2_0 = m2_0, lm1_1 = m1_1, lm2_1 = m2_1;
    const int   li1_0 = i1_0, li1_1 = i1_1;

    // ---- merge across the 4 quad-threads of each row ----
#pragma unroll
    for (int o = 1; o <= 2; o <<= 1) {
        float om1 = __shfl_xor_sync(0xFFFFFFFFu, m1_0, o);
        float om2 = __shfl_xor_sync(0xFFFFFFFFu, m2_0, o);
        m2_0 = fminf(fminf(m2_0, om2), fmaxf(m1_0, om1));
        m1_0 = fminf(m1_0, om1);
        float pm1 = __shfl_xor_sync(0xFFFFFFFFu, m1_1, o);
        float pm2 = __shfl_xor_sync(0xFFFFFFFFu, m2_1, o);
        m2_1 = fminf(fminf(m2_1, pm2), fmaxf(m1_1, pm1));
        m1_1 = fminf(m1_1, pm1);
    }
    const float thr0 = m1_0 + fmaf(sSab[r0], MARG_COEF, MARG_ABS);
    const float thr1 = m1_1 + fmaf(sSab[r1], MARG_COEF, MARG_ABS);

    // ---- queue candidates ----
    if (lm1_0 <= thr0) { int s = atomicAdd(&qn1, 1); if (s < Q1CAP) sQ1[s] = (r0 << 9) | li1_0; }
    if (lm1_1 <= thr1) { int s = atomicAdd(&qn1, 1); if (s < Q1CAP) sQ1[s] = (r1 << 9) | li1_1; }
    if (lm2_0 <= thr0) { int s = atomicAdd(&fn, 1);  if (s < FCAP)  sFl[s] = (r0 << 2) | q4; }
    if (lm2_1 <= thr1) { int s = atomicAdd(&fn, 1);  if (s < FCAP)  sFl[s] = (r1 << 2) | q4; }
    __syncthreads();

    // ---- coalesced warp-cooperative exact fp32 recheck ----
    // 8 lanes per code: lane d4 loads e[code*32 + d4*4 .. +3] (one 128B line per code)
#define COOP_CHECK(rowv, codev, valid) {                                          \
        int d4c = lane & 7;                                                       \
        float4 ev = *(const float4*)(en + (codev) * 32 + d4c * 4);                \
        float4 xv = *(const float4*)(sXf + (rowv) * 36 + d4c * 4);                \
        float p = xv.x * ev.x;                                                    \
        p = fmaf(xv.y, ev.y, p);                                                  \
        p = fmaf(xv.z, ev.z, p);                                                  \
        p = fmaf(xv.w, ev.w, p);                                                  \
        p += __shfl_xor_sync(0xFFFFFFFFu, p, 1);                                  \
        p += __shfl_xor_sync(0xFFFFFFFFu, p, 2);                                  \
        p += __shfl_xor_sync(0xFFFFFFFFu, p, 4);                                  \
        if (d4c == 0 && (valid)) {                                                \
            float dist = fmaf(p, -2.0f, sXsq[rowv] + sEsq[codev]);                \
            unsigned long long pk =                                               \
                ((unsigned long long)__float_as_uint(dist) << 32)                 \
                | (unsigned int)(codev);                                          \
            atomicMin(&sBest[rowv], pk);                                          \
        }                                                                         \
    }

    {   // singles: 4 entries per warp-iteration
        const int nq = (qn1 < Q1CAP) ? qn1 : Q1CAP;
        const int niter = (nq + 3) >> 2;
        for (int i = w; i < niter; i += 8) {
            int ei = i * 4 + (lane >> 3);
            int eic = (ei < nq) ? ei : (nq - 1);
            unsigned int ent = sQ1[eic];
            int row = ent >> 9, code = ent & 511;
            COOP_CHECK(row, code, ei < nq)
        }
    }
    {   // flagged ranges: 4 codes per warp-iteration, 32 iters per range
        const int nf = (fn < FCAP) ? fn : FCAP;
        for (int i = w; i < nf * 32; i += 8) {
            int e = i >> 5, kk = i & 31;
            unsigned int fl = sFl[e];
            int row = fl >> 2, q = fl & 3;
            int k = kk * 4 + (lane >> 3);
            int code = (k >> 1) * 8 + q * 2 + (k & 1);
            COOP_CHECK(row, code, 1)
        }
        if (fn > FCAP) {   // overflow fallback (margin math says never)
            for (int i = w; i < 128 * 128; i += 8) {
                int row = i >> 7, c4 = i & 127;
                int code = c4 * 4 + (lane >> 3);
                COOP_CHECK(row, code, 1)
            }
        }
    }
#undef COOP_CHECK
    __syncthreads();

    // ---- epilogue: outputs per position ----
    float lloss = 0.0f;
    if (tid < 128) {
        const int pp = tid;
        const int bi = (int)(sBest[pp] & 0xFFFFFFFFull);

        const int t = tile * 128 + pp;
        const int b = t >> 6, l = t & 63;
        out[OFF_IDX + (size_t)b * 256 + (size_t)n * 64 + l] = (float)bi;
        atomicAdd(&g_counts[n * M_CODES + bi], 1);

        float4* dwp = g_dw4 + ((size_t)n * M_CODES + bi) * 8;
        float*  zq  = out + OFF_ZQ + (size_t)b * 8192 + (size_t)n * 2048 + l;
        const float* xr = sXf + pp * 36;
        const float* er = en + bi * D_DIM;
#pragma unroll
        for (int d4 = 0; d4 < 8; d4++) {
            float xv0 = xr[d4 * 4 + 0], q0 = er[d4 * 4 + 0];
            float xv1 = xr[d4 * 4 + 1], q1 = er[d4 * 4 + 1];
            float xv2 = xr[d4 * 4 + 2], q2 = er[d4 * 4 + 2];
            float xv3 = xr[d4 * 4 + 3], q3 = er[d4 * 4 + 3];
            zq[(d4 * 4 + 0) * 64] = __fsub_rn(__fadd_rn(q0, xv0), xv0);
            zq[(d4 * 4 + 1) * 64] = __fsub_rn(__fadd_rn(q1, xv1), xv1);
            zq[(d4 * 4 + 2) * 64] = __fsub_rn(__fadd_rn(q2, xv2), xv2);
            zq[(d4 * 4 + 3) * 64] = __fsub_rn(__fadd_rn(q3, xv3), xv3);
            float f0 = xv0 - q0, f1 = xv1 - q1, f2 = xv2 - q2, f3 = xv3 - q3;
            lloss = fmaf(f0, f0, lloss);
            lloss = fmaf(f1, f1, lloss);
            lloss = fmaf(f2, f2, lloss);
            lloss = fmaf(f3, f3, lloss);
            atomicAdd(dwp + d4, make_float4(xv0, xv1, xv2, xv3));
        }
    }

    // ---- CTA loss reduction -> one double atomic ----
#pragma unroll
    for (int o = 16; o > 0; o >>= 1) lloss += __shfl_down_sync(0xFFFFFFFFu, lloss, o);
    if (lane == 0) sWs[w] = lloss;
    __syncthreads();
    if (tid == 0) {
        double s = 0.0;
#pragma unroll
        for (int ww = 0; ww < 8; ww++) s += (double)sWs[ww];
        atomicAdd(&g_loss, s);
    }
}

// ---------------- kernel 2: EMA / Laplace / embedding / perplexity / loss ----------------
__global__ void vq_fin(const float* __restrict__ ema_c,
                       const float* __restrict__ ema_w,
                       float* __restrict__ out) {
    const int n = blockIdx.x;
    const int m = threadIdx.x;
    __shared__ float red[M_CODES];
    const float* g_dwf = (const float*)g_dw4;

    const float DECAY = 0.999f;
    const float OMD   = (float)(1.0 - 0.999);
    const float MEPS  = (float)(512.0 * 1e-5);

    float cnt  = (float)g_counts[n * M_CODES + m];
    float cnew = DECAY * ema_c[n * M_CODES + m] + OMD * cnt;

    red[m] = cnew;
    __syncthreads();
    for (int s = 256; s > 0; s >>= 1) {
        if (m < s) red[m] += red[m + s];
        __syncthreads();
    }
    float ntot = red[0];
    __syncthreads();

    float clap = (cnew + 1e-5f) / (ntot + MEPS) * ntot;
    out[OFF_CNT + (size_t)n * M_CODES + m] = clap;

#pragma unroll
    for (int d = 0; d < D_DIM; d++) {
        size_t idx = ((size_t)n * M_CODES + m) * D_DIM + d;
        float wv = DECAY * ema_w[idx] + OMD * g_dwf[idx];
        out[OFF_W + idx]   = wv;
        out[OFF_EMB + idx] = wv / clap;
    }

    float p    = cnt * (1.0f / 65536.0f);
    float term = p * logf(p + 1e-10f);
    red[m] = term;
    __syncthreads();
    for (int s = 256; s > 0; s >>= 1) {
        if (m < s) red[m] += red[m + s];
        __syncthreads();
    }
    if (m == 0) {
        atomicAdd(&out[OFF_PERP], expf(-red[0]));
        if (n == 0) out[OFF_LOSS] = (float)(0.25 * g_loss * (1.0 / 8388608.0));
    }
}

// ---------------- launch ----------------
extern "C" void kernel_launch(void* const* d_in, const int* in_sizes, int n_in,
                              void* d_out, int out_size) {
    const float* x     = (const float*)d_in[0];
    const float* emb   = (const float*)d_in[1];
    const float* ema_c = (const float*)d_in[2];
    const float* ema_w = (const float*)d_in[3];
    float* out = (float*)d_out;

    cudaFuncSetAttribute(vq_main, cudaFuncAttributeMaxDynamicSharedMemorySize, SMEM_BYTES);

    vq_zero<<<256, 256>>>(out);
    vq_main<<<dim3(T_POS / 128, N_CB), 256, SMEM_BYTES>>>(x, emb, out);
    vq_fin<<<N_CB, M_CODES>>>(ema_c, ema_w, out);
}

// round 13
// speedup vs baseline: 4.5737x; 1.1384x over previous
#include <cuda_runtime.h>
#include <cstdint>

// ---------------- problem constants ----------------
#define N_CB 4
#define M_CODES 512
#define D_DIM 32
#define T_POS 65536
#define POS_CTA 256
#define THREADS 512

// output layout (float32, reference tuple order, flattened+concatenated)
#define OFF_ZQ   0ULL
#define OFF_LOSS 8388608ULL
#define OFF_PERP 8388609ULL
#define OFF_IDX  8388610ULL
#define OFF_EMB  8650754ULL
#define OFF_CNT  8716290ULL
#define OFF_W    8718338ULL

// fragment-permuted slot: d = kt*8 + 4*h + q4  ->  slot = q4*8 + kt*2 + h
#define SLOT(d) (((d) & 3) * 8 + ((d) >> 3) * 2 + (((d) >> 2) & 1))

// ---------------- smem layout (float offsets), stride 36 rows ----------------
#define SXP_F   0        // x  [256 pos][36] (permuted)     9216 floats
#define SE_F    9216     // e  [512 code][36] (permuted)   18432 floats
#define SESQ_F  27648    // esq[512]
#define SXSQ_F  28160    // xsq[256]
#define SSAB_F  28416    // sum|x| [256]
#define SBEST_F 28672    // u64[256] packed (dist,code)
#define SFL_F   29184    // flag list u32[256]
#define SWS_F   29440    // warp loss partials [16]
#define SMEM_FLOATS 29456
#define SMEM_BYTES (SMEM_FLOATS * 4)   // 117824 -> 1 CTA/SM, 16 warps

#define FLT_BIG 3.402823466e38f
#define MARG_COEF 1.6e-4f
#define MARG_ABS  5e-5f
#define FCAP 256

// ---------------- scratch ----------------
__device__ int    g_counts[N_CB * M_CODES];
__device__ float4 g_dw4[N_CB * M_CODES * 8];
__device__ double g_loss;

// ---------------- kernel 0: zero scratch ----------------
__global__ void vq_zero(float* __restrict__ out) {
    int i = blockIdx.x * blockDim.x + threadIdx.x;
    float* dw = (float*)g_dw4;
    if (i < N_CB * M_CODES * D_DIM) dw[i] = 0.0f;
    if (i < N_CB * M_CODES)         g_counts[i] = 0;
    if (i == 0) { g_loss = 0.0; out[OFF_PERP] = 0.0f; }
}

// ---------------- kernel 1: tf32 single-sweep top-2 + exact recheck (256 pos/CTA) ----------------
__global__ void __launch_bounds__(THREADS) vq_main(const float* __restrict__ x,
                                                   const float* __restrict__ emb,
                                                   float* __restrict__ out) {
    extern __shared__ float sm[];
    __shared__ int fn;
    float* sX   = sm + SXP_F;
    float* sE   = sm + SE_F;
    float* sEsq = sm + SESQ_F;
    float* sXsq = sm + SXSQ_F;
    float* sSab = sm + SSAB_F;
    unsigned long long* sBest = (unsigned long long*)(sm + SBEST_F);
    unsigned int* sFl = (unsigned int*)(sm + SFL_F);
    float* sWs  = sm + SWS_F;

    const int n    = blockIdx.y;
    const int tile = blockIdx.x;
    const int tid  = threadIdx.x;
    const int w    = tid >> 5;
    const int lane = tid & 31;
    const int g    = lane >> 2;
    const int q4   = lane & 3;

    // ---- fill x tile (permuted layout): 256 positions ----
    for (int i = tid; i < POS_CTA * D_DIM; i += THREADS) {
        int d = i >> 8, p = i & 255;
        int t = tile * POS_CTA + p;
        sX[p * 36 + SLOT(d)] = x[(size_t)(t >> 6) * 8192 + (size_t)n * 2048 + d * 64 + (t & 63)];
    }
    // ---- fill codebook (permuted layout) ----
    const float* en = emb + (size_t)n * M_CODES * D_DIM;
    for (int i = tid; i < M_CODES * D_DIM; i += THREADS) {
        int m = i >> 5, d = i & 31;
        sE[m * 36 + SLOT(d)] = en[i];
    }
    if (tid == 0) fn = 0;
    __syncthreads();

    // ---- esq: ascending-d fmaf chain (reference-matching), one code per thread ----
    {
        const int c = tid;
        if (c < M_CODES) {
            const float* er = sE + c * 36;
            float s = 0.0f;
#pragma unroll
            for (int d = 0; d < D_DIM; d++) {
                float v = er[SLOT(d)];
                s = fmaf(v, v, s);
            }
            sEsq[c] = s;
        }
    }
    // ---- xsq + sum|x| + sBest init ----
    if (tid < POS_CTA) {
        const float* xr = sX + tid * 36;
        float s = 0.0f, a = 0.0f;
#pragma unroll
        for (int d = 0; d < D_DIM; d++) {
            float v = xr[SLOT(d)];
            s = fmaf(v, v, s);
            a += fabsf(v);
        }
        sXsq[tid] = s;
        sSab[tid] = a;
        sBest[tid] = 0xFFFFFFFFFFFFFFFFull;
    }
    __syncthreads();

    // ---- A fragments (4 x LDS.128 per thread); warp w owns rows [16w, 16w+16) ----
    const int r0 = w * 16 + g;
    const int r1 = r0 + 8;
    float4 xa0 = *(const float4*)&sX[r0 * 36 + q4 * 8];
    float4 xa1 = *(const float4*)&sX[r0 * 36 + q4 * 8 + 4];
    float4 xb0 = *(const float4*)&sX[r1 * 36 + q4 * 8];
    float4 xb1 = *(const float4*)&sX[r1 * 36 + q4 * 8 + 4];
    float af0[4], af1[4], af2[4], af3[4];
    af0[0] = xa0.x; af2[0] = xa0.y; af0[1] = xa0.z; af2[1] = xa0.w;
    af0[2] = xa1.x; af2[2] = xa1.y; af0[3] = xa1.z; af2[3] = xa1.w;
    af1[0] = xb0.x; af3[0] = xb0.y; af1[1] = xb0.z; af3[1] = xb0.w;
    af1[2] = xb1.x; af3[2] = xb1.y; af1[3] = xb1.z; af3[3] = xb1.w;

    const float* peB = sE + g * 36 + q4 * 8;   // advances 288 per nt

    // ---- single branchless sweep: top-2 values + top-1 index per row ----
    float m1_0 = FLT_BIG, m2_0 = FLT_BIG, m1_1 = FLT_BIG, m2_1 = FLT_BIG;
    int   i1_0 = 0, i1_1 = 0;

#pragma unroll 4
    for (int nt = 0; nt < 64; nt++) {
        float c0 = 0.0f, c1 = 0.0f, c2 = 0.0f, c3 = 0.0f;
        {
            float4 e0 = *(const float4*)(peB + nt * 288);
            float4 e1 = *(const float4*)(peB + nt * 288 + 4);
            float bb[8] = {e0.x, e0.y, e0.z, e0.w, e1.x, e1.y, e1.z, e1.w};
#pragma unroll
            for (int kt = 0; kt < 4; kt++) {
                asm volatile(
                    "mma.sync.aligned.m16n8k8.row.col.f32.tf32.tf32.f32 "
                    "{%0,%1,%2,%3}, {%4,%5,%6,%7}, {%8,%9}, {%0,%1,%2,%3};"
                    : "+f"(c0), "+f"(c1), "+f"(c2), "+f"(c3)
                    : "f"(af0[kt]), "f"(af1[kt]), "f"(af2[kt]), "f"(af3[kt]),
                      "f"(bb[2 * kt]), "f"(bb[2 * kt + 1]));
            }
        }
        const int col0 = nt * 8 + q4 * 2;
        float2 e2 = *(const float2*)&sEsq[col0];
        float d00 = fmaf(c0, -2.0f, e2.x);
        float d01 = fmaf(c1, -2.0f, e2.y);
        float d10 = fmaf(c2, -2.0f, e2.x);
        float d11 = fmaf(c3, -2.0f, e2.y);

        {   // row 0: branchless top-2 + index of min
            float lo = fminf(d00, d01);
            float hi = fmaxf(d00, d01);
            int  ilo = (d01 < d00) ? (col0 + 1) : col0;
            m2_0 = fminf(m2_0, fminf(hi, fmaxf(lo, m1_0)));
            i1_0 = (lo < m1_0) ? ilo : i1_0;
            m1_0 = fminf(m1_0, lo);
        }
        {   // row 1
            float lo = fminf(d10, d11);
            float hi = fmaxf(d10, d11);
            int  ilo = (d11 < d10) ? (col0 + 1) : col0;
            m2_1 = fminf(m2_1, fminf(hi, fmaxf(lo, m1_1)));
            i1_1 = (lo < m1_1) ? ilo : i1_1;
            m1_1 = fminf(m1_1, lo);
        }
    }

    // save thread-local pre-merge state (recheck decisions use these)
    const float lm1_0 = m1_0, lm2_0 = m2_0, lm1_1 = m1_1, lm2_1 = m2_1;
    const int   li1_0 = i1_0, li1_1 = i1_1;

    // ---- merge across the 4 quad-threads of each row ----
#pragma unroll
    for (int o = 1; o <= 2; o <<= 1) {
        float om1 = __shfl_xor_sync(0xFFFFFFFFu, m1_0, o);
        float om2 = __shfl_xor_sync(0xFFFFFFFFu, m2_0, o);
        m2_0 = fminf(fminf(m2_0, om2), fmaxf(m1_0, om1));
        m1_0 = fminf(m1_0, om1);
        float pm1 = __shfl_xor_sync(0xFFFFFFFFu, m1_1, o);
        float pm2 = __shfl_xor_sync(0xFFFFFFFFu, m2_1, o);
        m2_1 = fminf(fminf(m2_1, pm2), fmaxf(m1_1, pm1));
        m1_1 = fminf(m1_1, pm1);
    }
    const float thr0 = m1_0 + fmaf(sSab[r0], MARG_COEF, MARG_ABS);
    const float thr1 = m1_1 + fmaf(sSab[r1], MARG_COEF, MARG_ABS);

    // ---- exact fp32 recheck of per-thread minima; flag ranges with 2nd-in-margin ----
#define EXACT_CHECK(row, code) {                                                  \
        const float* xr = sX + (row) * 36;                                        \
        const float* er = sE + (code) * 36;                                       \
        float dot = 0.0f;                                                         \
        _Pragma("unroll")                                                         \
        for (int d = 0; d < D_DIM; d++)                                           \
            dot = fmaf(xr[SLOT(d)], er[SLOT(d)], dot);                            \
        float dist = fmaf(dot, -2.0f, sXsq[row] + sEsq[code]);                    \
        unsigned long long pk = ((unsigned long long)__float_as_uint(dist) << 32) \
                                | (unsigned int)(code);                           \
        atomicMin(&sBest[row], pk);                                               \
    }

    if (lm1_0 <= thr0) EXACT_CHECK(r0, li1_0)
    if (lm1_1 <= thr1) EXACT_CHECK(r1, li1_1)
    if (lm2_0 <= thr0) { int s = atomicAdd(&fn, 1); if (s < FCAP) sFl[s] = (r0 << 2) | q4; }
    if (lm2_1 <= thr1) { int s = atomicAdd(&fn, 1); if (s < FCAP) sFl[s] = (r1 << 2) | q4; }
    __syncthreads();

    // ---- cooperative exact rescan of flagged (row, quad) 128-code ranges ----
    {
        const int nf = (fn < FCAP) ? fn : FCAP;
        for (int i = tid; i < nf * 128; i += THREADS) {
            const int e = i >> 7, k = i & 127;
            const unsigned int fl = sFl[e];
            const int row = fl >> 2, q = fl & 3;
            const int code = (k >> 1) * 8 + q * 2 + (k & 1);
            EXACT_CHECK(row, code)
        }
        if (fn > FCAP) {   // overflow fallback (practically never)
            for (int i = tid; i < POS_CTA * M_CODES; i += THREADS) {
                EXACT_CHECK(i >> 9, i & 511)
            }
        }
    }
#undef EXACT_CHECK
    __syncthreads();

    // ---- epilogue: outputs per position (threads 0..255) ----
    float lloss = 0.0f;
    if (tid < POS_CTA) {
        const int pp = tid;
        const int bi = (int)(sBest[pp] & 0xFFFFFFFFull);

        const int t = tile * POS_CTA + pp;
        const int b = t >> 6, l = t & 63;
        out[OFF_IDX + (size_t)b * 256 + (size_t)n * 64 + l] = (float)bi;
        atomicAdd(&g_counts[n * M_CODES + bi], 1);

        float4* dwp = g_dw4 + ((size_t)n * M_CODES + bi) * 8;
        float*  zq  = out + OFF_ZQ + (size_t)b * 8192 + (size_t)n * 2048 + l;
        const float* xr = sX + pp * 36;
        const float* er = sE + bi * 36;
#pragma unroll
        for (int d4 = 0; d4 < 8; d4++) {
            float xv0 = xr[SLOT(d4 * 4 + 0)], q0 = er[SLOT(d4 * 4 + 0)];
            float xv1 = xr[SLOT(d4 * 4 + 1)], q1 = er[SLOT(d4 * 4 + 1)];
            float xv2 = xr[SLOT(d4 * 4 + 2)], q2 = er[SLOT(d4 * 4 + 2)];
            float xv3 = xr[SLOT(d4 * 4 + 3)], q3 = er[SLOT(d4 * 4 + 3)];
            zq[(d4 * 4 + 0) * 64] = __fsub_rn(__fadd_rn(q0, xv0), xv0);
            zq[(d4 * 4 + 1) * 64] = __fsub_rn(__fadd_rn(q1, xv1), xv1);
            zq[(d4 * 4 + 2) * 64] = __fsub_rn(__fadd_rn(q2, xv2), xv2);
            zq[(d4 * 4 + 3) * 64] = __fsub_rn(__fadd_rn(q3, xv3), xv3);
            float f0 = xv0 - q0, f1 = xv1 - q1, f2 = xv2 - q2, f3 = xv3 - q3;
            lloss = fmaf(f0, f0, lloss);
            lloss = fmaf(f1, f1, lloss);
            lloss = fmaf(f2, f2, lloss);
            lloss = fmaf(f3, f3, lloss);
            atomicAdd(dwp + d4, make_float4(xv0, xv1, xv2, xv3));
        }
    }

    // ---- CTA loss reduction -> one double atomic ----
#pragma unroll
    for (int o = 16; o > 0; o >>= 1) lloss += __shfl_down_sync(0xFFFFFFFFu, lloss, o);
    if (lane == 0) sWs[w] = lloss;
    __syncthreads();
    if (tid == 0) {
        double s = 0.0;
#pragma unroll
        for (int ww = 0; ww < 16; ww++) s += (double)sWs[ww];
        atomicAdd(&g_loss, s);
    }
}

// ---------------- kernel 2: EMA / Laplace / embedding / perplexity / loss ----------------
__global__ void vq_fin(const float* __restrict__ ema_c,
                       const float* __restrict__ ema_w,
                       float* __restrict__ out) {
    const int n = blockIdx.x;
    const int m = threadIdx.x;
    __shared__ float red[M_CODES];
    const float* g_dwf = (const float*)g_dw4;

    const float DECAY = 0.999f;
    const float OMD   = (float)(1.0 - 0.999);
    const float MEPS  = (float)(512.0 * 1e-5);

    float cnt  = (float)g_counts[n * M_CODES + m];
    float cnew = DECAY * ema_c[n * M_CODES + m] + OMD * cnt;

    red[m] = cnew;
    __syncthreads();
    for (int s = 256; s > 0; s >>= 1) {
        if (m < s) red[m] += red[m + s];
        __syncthreads();
    }
    float ntot = red[0];
    __syncthreads();

    float clap = (cnew + 1e-5f) / (ntot + MEPS) * ntot;
    out[OFF_CNT + (size_t)n * M_CODES + m] = clap;

#pragma unroll
    for (int d = 0; d < D_DIM; d++) {
        size_t idx = ((size_t)n * M_CODES + m) * D_DIM + d;
        float wv = DECAY * ema_w[idx] + OMD * g_dwf[idx];
        out[OFF_W + idx]   = wv;
        out[OFF_EMB + idx] = wv / clap;
    }

    float p    = cnt * (1.0f / 65536.0f);
    float term = p * logf(p + 1e-10f);
    red[m] = term;
    __syncthreads();
    for (int s = 256; s > 0; s >>= 1) {
        if (m < s) red[m] += red[m + s];
        __syncthreads();
    }
    if (m == 0) {
        atomicAdd(&out[OFF_PERP], expf(-red[0]));
        if (n == 0) out[OFF_LOSS] = (float)(0.25 * g_loss * (1.0 / 8388608.0));
    }
}

// ---------------- launch ----------------
extern "C" void kernel_launch(void* const* d_in, const int* in_sizes, int n_in,
                              void* d_out, int out_size) {
    const float* x     = (const float*)d_in[0];
    const float* emb   = (const float*)d_in[1];
    const float* ema_c = (const float*)d_in[2];
    const float* ema_w = (const float*)d_in[3];
    float* out = (float*)d_out;

    cudaFuncSetAttribute(vq_main, cudaFuncAttributeMaxDynamicSharedMemorySize, SMEM_BYTES);

    vq_zero<<<256, 256>>>(out);
    vq_main<<<dim3(T_POS / POS_CTA, N_CB), THREADS, SMEM_BYTES>>>(x, emb, out);
    vq_fin<<<N_CB, M_CODES>>>(ema_c, ema_w, out);
}

// round 14
// speedup vs baseline: 4.6050x; 1.0068x over previous
#include <cuda_runtime.h>
#include <cstdint>

// ---------------- problem constants ----------------
#define N_CB 4
#define M_CODES 512
#define D_DIM 32
#define T_POS 65536

// output layout (float32, reference tuple order, flattened+concatenated)
#define OFF_ZQ   0ULL
#define OFF_LOSS 8388608ULL
#define OFF_PERP 8388609ULL
#define OFF_IDX  8388610ULL
#define OFF_EMB  8650754ULL
#define OFF_CNT  8716290ULL
#define OFF_W    8718338ULL

// fragment-permuted slot: d = kt*8 + 4*h + q4  ->  slot = q4*8 + kt*2 + h
#define SLOT(d) (((d) & 3) * 8 + ((d) >> 3) * 2 + (((d) >> 2) & 1))

// ---------------- smem layout (float offsets), stride 36 rows ----------------
#define SXP_F   0        // x  [128 pos][36]  (permuted)   4608
#define SE_F    4608     // e  [512 code][36] (permuted)  18432
#define SESQ_F  23040    // esq[512]
#define SXSQ_F  23552    // xsq[128]
#define SSAB_F  23680    // sum|x| [128]
#define SBEST_F 23808    // u64[128] packed (dist,code)
#define SFL_F   24064    // flag list u32[128]
#define SWS_F   24192    // warp loss partials [8]
#define SMEM_FLOATS 24200
#define SMEM_BYTES (SMEM_FLOATS * 4)   // 96800 -> 2 CTAs/SM

#define FLT_BIG 3.402823466e38f
#define MARG_COEF 1.6e-4f
#define MARG_ABS  5e-5f
#define FCAP 128

// ---------------- scratch (zero at load; vq_fin re-zeroes after use each run) ----------------
__device__ int    g_counts[N_CB * M_CODES];
__device__ float4 g_dw4[N_CB * M_CODES * 8];
__device__ double g_loss;

// ---------------- kernel 1: single-sweep tf32 mma (split chains), top-2, exact recheck ----------------
__global__ void __launch_bounds__(256) vq_main(const float* __restrict__ x,
                                               const float* __restrict__ emb,
                                               float* __restrict__ out) {
    extern __shared__ float sm[];
    __shared__ int fn;
    float* sX   = sm + SXP_F;
    float* sE   = sm + SE_F;
    float* sEsq = sm + SESQ_F;
    float* sXsq = sm + SXSQ_F;
    float* sSab = sm + SSAB_F;
    unsigned long long* sBest = (unsigned long long*)(sm + SBEST_F);
    unsigned int* sFl = (unsigned int*)(sm + SFL_F);
    float* sWs  = sm + SWS_F;

    const int n    = blockIdx.y;
    const int tile = blockIdx.x;
    const int tid  = threadIdx.x;
    const int w    = tid >> 5;
    const int lane = tid & 31;
    const int g    = lane >> 2;
    const int q4   = lane & 3;

    // out[OFF_PERP] must be zero before vq_fin accumulates into it
    if (tile == 0 && n == 0 && tid == 0) out[OFF_PERP] = 0.0f;

    // ---- fill x tile (permuted layout) ----
    for (int i = tid; i < 128 * D_DIM; i += 256) {
        int d = i >> 7, p = i & 127;
        int t = tile * 128 + p;
        sX[p * 36 + SLOT(d)] = x[(size_t)(t >> 6) * 8192 + (size_t)n * 2048 + d * 64 + (t & 63)];
    }
    // ---- fill codebook (permuted layout) ----
    const float* en = emb + (size_t)n * M_CODES * D_DIM;
    for (int i = tid; i < M_CODES * D_DIM; i += 256) {
        int m = i >> 5, d = i & 31;
        sE[m * 36 + SLOT(d)] = en[i];
    }
    if (tid == 0) fn = 0;
    __syncthreads();

    // ---- esq: ascending-d fmaf chain (reference-matching) ----
    for (int c = tid; c < M_CODES; c += 256) {
        const float* er = sE + c * 36;
        float s = 0.0f;
#pragma unroll
        for (int d = 0; d < D_DIM; d++) {
            float v = er[SLOT(d)];
            s = fmaf(v, v, s);
        }
        sEsq[c] = s;
    }
    // ---- xsq + sum|x| + sBest init ----
    if (tid < 128) {
        const float* xr = sX + tid * 36;
        float s = 0.0f, a = 0.0f;
#pragma unroll
        for (int d = 0; d < D_DIM; d++) {
            float v = xr[SLOT(d)];
            s = fmaf(v, v, s);
            a += fabsf(v);
        }
        sXsq[tid] = s;
        sSab[tid] = a;
        sBest[tid] = 0xFFFFFFFFFFFFFFFFull;
    }
    __syncthreads();

    // ---- A fragments (4 x LDS.128 per thread) ----
    const int r0 = w * 16 + g;
    const int r1 = r0 + 8;
    float4 xa0 = *(const float4*)&sX[r0 * 36 + q4 * 8];
    float4 xa1 = *(const float4*)&sX[r0 * 36 + q4 * 8 + 4];
    float4 xb0 = *(const float4*)&sX[r1 * 36 + q4 * 8];
    float4 xb1 = *(const float4*)&sX[r1 * 36 + q4 * 8 + 4];
    float af0[4], af1[4], af2[4], af3[4];
    af0[0] = xa0.x; af2[0] = xa0.y; af0[1] = xa0.z; af2[1] = xa0.w;
    af0[2] = xa1.x; af2[2] = xa1.y; af0[3] = xa1.z; af2[3] = xa1.w;
    af1[0] = xb0.x; af3[0] = xb0.y; af1[1] = xb0.z; af3[1] = xb0.w;
    af1[2] = xb1.x; af3[2] = xb1.y; af1[3] = xb1.z; af3[3] = xb1.w;

    const float* peB = sE + g * 36 + q4 * 8;   // advances 288 per nt

    // ---- single branchless sweep: split accumulator chains (depth 2, not 4) ----
    float m1_0 = FLT_BIG, m2_0 = FLT_BIG, m1_1 = FLT_BIG, m2_1 = FLT_BIG;
    int   i1_0 = 0, i1_1 = 0;

#pragma unroll 4
    for (int nt = 0; nt < 64; nt++) {
        float a0 = 0.0f, a1 = 0.0f, a2 = 0.0f, a3 = 0.0f;
        float b0 = 0.0f, b1 = 0.0f, b2 = 0.0f, b3 = 0.0f;
        {
            float4 e0 = *(const float4*)(peB + nt * 288);
            float4 e1 = *(const float4*)(peB + nt * 288 + 4);
            float bbf[8] = {e0.x, e0.y, e0.z, e0.w, e1.x, e1.y, e1.z, e1.w};
            // chain A: kt = 0,1
#pragma unroll
            for (int kt = 0; kt < 2; kt++) {
                asm volatile(
                    "mma.sync.aligned.m16n8k8.row.col.f32.tf32.tf32.f32 "
                    "{%0,%1,%2,%3}, {%4,%5,%6,%7}, {%8,%9}, {%0,%1,%2,%3};"
                    : "+f"(a0), "+f"(a1), "+f"(a2), "+f"(a3)
                    : "f"(af0[kt]), "f"(af1[kt]), "f"(af2[kt]), "f"(af3[kt]),
                      "f"(bbf[2 * kt]), "f"(bbf[2 * kt + 1]));
            }
            // chain B: kt = 2,3 (independent of chain A)
#pragma unroll
            for (int kt = 2; kt < 4; kt++) {
                asm volatile(
                    "mma.sync.aligned.m16n8k8.row.col.f32.tf32.tf32.f32 "
                    "{%0,%1,%2,%3}, {%4,%5,%6,%7}, {%8,%9}, {%0,%1,%2,%3};"
                    : "+f"(b0), "+f"(b1), "+f"(b2), "+f"(b3)
                    : "f"(af0[kt]), "f"(af1[kt]), "f"(af2[kt]), "f"(af3[kt]),
                      "f"(bbf[2 * kt]), "f"(bbf[2 * kt + 1]));
            }
        }
        float c0 = a0 + b0, c1 = a1 + b1, c2 = a2 + b2, c3 = a3 + b3;

        const int col0 = nt * 8 + q4 * 2;
        float2 e2 = *(const float2*)&sEsq[col0];
        float d00 = fmaf(c0, -2.0f, e2.x);
        float d01 = fmaf(c1, -2.0f, e2.y);
        float d10 = fmaf(c2, -2.0f, e2.x);
        float d11 = fmaf(c3, -2.0f, e2.y);

        {   // row 0: branchless top-2 + index of min
            float lo = fminf(d00, d01);
            float hi = fmaxf(d00, d01);
            int  ilo = (d01 < d00) ? (col0 + 1) : col0;
            m2_0 = fminf(m2_0, fminf(hi, fmaxf(lo, m1_0)));
            i1_0 = (lo < m1_0) ? ilo : i1_0;
            m1_0 = fminf(m1_0, lo);
        }
        {   // row 1
            float lo = fminf(d10, d11);
            float hi = fmaxf(d10, d11);
            int  ilo = (d11 < d10) ? (col0 + 1) : col0;
            m2_1 = fminf(m2_1, fminf(hi, fmaxf(lo, m1_1)));
            i1_1 = (lo < m1_1) ? ilo : i1_1;
            m1_1 = fminf(m1_1, lo);
        }
    }

    // save thread-local pre-merge state (recheck decisions use these)
    const float lm1_0 = m1_0, lm2_0 = m2_0, lm1_1 = m1_1, lm2_1 = m2_1;
    const int   li1_0 = i1_0, li1_1 = i1_1;

    // ---- merge across the 4 quad-threads of each row ----
#pragma unroll
    for (int o = 1; o <= 2; o <<= 1) {
        float om1 = __shfl_xor_sync(0xFFFFFFFFu, m1_0, o);
        float om2 = __shfl_xor_sync(0xFFFFFFFFu, m2_0, o);
        m2_0 = fminf(fminf(m2_0, om2), fmaxf(m1_0, om1));
        m1_0 = fminf(m1_0, om1);
        float pm1 = __shfl_xor_sync(0xFFFFFFFFu, m1_1, o);
        float pm2 = __shfl_xor_sync(0xFFFFFFFFu, m2_1, o);
        m2_1 = fminf(fminf(m2_1, pm2), fmaxf(m1_1, pm1));
        m1_1 = fminf(m1_1, pm1);
    }
    const float thr0 = m1_0 + fmaf(sSab[r0], MARG_COEF, MARG_ABS);
    const float thr1 = m1_1 + fmaf(sSab[r1], MARG_COEF, MARG_ABS);

    // ---- exact fp32 recheck of per-thread minima; flag ranges with 2nd-in-margin ----
#define EXACT_CHECK(row, code) {                                                  \
        const float* xr = sX + (row) * 36;                                        \
        const float* er = sE + (code) * 36;                                       \
        float dot = 0.0f;                                                         \
        _Pragma("unroll")                                                         \
        for (int d = 0; d < D_DIM; d++)                                           \
            dot = fmaf(xr[SLOT(d)], er[SLOT(d)], dot);                            \
        float dist = fmaf(dot, -2.0f, sXsq[row] + sEsq[code]);                    \
        unsigned long long pk = ((unsigned long long)__float_as_uint(dist) << 32) \
                                | (unsigned int)(code);                           \
        atomicMin(&sBest[row], pk);                                               \
    }

    if (lm1_0 <= thr0) EXACT_CHECK(r0, li1_0)
    if (lm1_1 <= thr1) EXACT_CHECK(r1, li1_1)
    if (lm2_0 <= thr0) { int s = atomicAdd(&fn, 1); if (s < FCAP) sFl[s] = (r0 << 2) | q4; }
    if (lm2_1 <= thr1) { int s = atomicAdd(&fn, 1); if (s < FCAP) sFl[s] = (r1 << 2) | q4; }
    __syncthreads();

    // ---- cooperative exact rescan of flagged (row, quad) 128-code ranges ----
    {
        const int nf = (fn < FCAP) ? fn : FCAP;
        for (int i = tid; i < nf * 128; i += 256) {
            const int e = i >> 7, k = i & 127;
            const unsigned int fl = sFl[e];
            const int row = fl >> 2, q = fl & 3;
            const int code = (k >> 1) * 8 + q * 2 + (k & 1);
            EXACT_CHECK(row, code)
        }
        if (fn > FCAP) {   // overflow fallback (practically never)
            for (int i = tid; i < 128 * M_CODES; i += 256) {
                EXACT_CHECK(i >> 9, i & 511)
            }
        }
    }
#undef EXACT_CHECK
    __syncthreads();

    // ---- epilogue: outputs per position ----
    float lloss = 0.0f;
    if (tid < 128) {
        const int pp = tid;
        const int bi = (int)(sBest[pp] & 0xFFFFFFFFull);

        const int t = tile * 128 + pp;
        const int b = t >> 6, l = t & 63;
        out[OFF_IDX + (size_t)b * 256 + (size_t)n * 64 + l] = (float)bi;
        atomicAdd(&g_counts[n * M_CODES + bi], 1);

        float4* dwp = g_dw4 + ((size_t)n * M_CODES + bi) * 8;
        float*  zq  = out + OFF_ZQ + (size_t)b * 8192 + (size_t)n * 2048 + l;
        const float* xr = sX + pp * 36;
        const float* er = sE + bi * 36;
#pragma unroll
        for (int d4 = 0; d4 < 8; d4++) {
            float xv0 = xr[SLOT(d4 * 4 + 0)], q0 = er[SLOT(d4 * 4 + 0)];
            float xv1 = xr[SLOT(d4 * 4 + 1)], q1 = er[SLOT(d4 * 4 + 1)];
            float xv2 = xr[SLOT(d4 * 4 + 2)], q2 = er[SLOT(d4 * 4 + 2)];
            float xv3 = xr[SLOT(d4 * 4 + 3)], q3 = er[SLOT(d4 * 4 + 3)];
            zq[(d4 * 4 + 0) * 64] = __fsub_rn(__fadd_rn(q0, xv0), xv0);
            zq[(d4 * 4 + 1) * 64] = __fsub_rn(__fadd_rn(q1, xv1), xv1);
            zq[(d4 * 4 + 2) * 64] = __fsub_rn(__fadd_rn(q2, xv2), xv2);
            zq[(d4 * 4 + 3) * 64] = __fsub_rn(__fadd_rn(q3, xv3), xv3);
            float f0 = xv0 - q0, f1 = xv1 - q1, f2 = xv2 - q2, f3 = xv3 - q3;
            lloss = fmaf(f0, f0, lloss);
            lloss = fmaf(f1, f1, lloss);
            lloss = fmaf(f2, f2, lloss);
            lloss = fmaf(f3, f3, lloss);
            atomicAdd(dwp + d4, make_float4(xv0, xv1, xv2, xv3));
        }
    }

    // ---- CTA loss reduction -> one double atomic ----
#pragma unroll
    for (int o = 16; o > 0; o >>= 1) lloss += __shfl_down_sync(0xFFFFFFFFu, lloss, o);
    if (lane == 0) sWs[w] = lloss;
    __syncthreads();
    if (tid == 0) {
        double s = 0.0;
#pragma unroll
        for (int ww = 0; ww < 8; ww++) s += (double)sWs[ww];
        atomicAdd(&g_loss, s);
    }
}

// ---------------- kernel 2: EMA / Laplace / embedding / perplexity / loss ----------------
// Also re-zeroes the scratch it consumed, so the next graph replay starts clean.
__global__ void vq_fin(const float* __restrict__ ema_c,
                       const float* __restrict__ ema_w,
                       float* __restrict__ out) {
    const int n = blockIdx.x;
    const int m = threadIdx.x;
    __shared__ float red[M_CODES];
    float* g_dwf = (float*)g_dw4;

    const float DECAY = 0.999f;
    const float OMD   = (float)(1.0 - 0.999);
    const float MEPS  = (float)(512.0 * 1e-5);

    const int ci = n * M_CODES + m;
    float cnt  = (float)g_counts[ci];
    g_counts[ci] = 0;                       // reset for next replay
    float cnew = DECAY * ema_c[ci] + OMD * cnt;

    red[m] = cnew;
    __syncthreads();
    for (int s = 256; s > 0; s >>= 1) {
        if (m < s) red[m] += red[m + s];
        __syncthreads();
    }
    float ntot = red[0];
    __syncthreads();

    float clap = (cnew + 1e-5f) / (ntot + MEPS) * ntot;
    out[OFF_CNT + (size_t)ci] = clap;

#pragma unroll
    for (int d = 0; d < D_DIM; d++) {
        size_t idx = (size_t)ci * D_DIM + d;
        float wv = DECAY * ema_w[idx] + OMD * g_dwf[idx];
        g_dwf[idx] = 0.0f;                  // reset for next replay
        out[OFF_W + idx]   = wv;
        out[OFF_EMB + idx] = wv / clap;
    }

    float p    = cnt * (1.0f / 65536.0f);
    float term = p * logf(p + 1e-10f);
    red[m] = term;
    __syncthreads();
    for (int s = 256; s > 0; s >>= 1) {
        if (m < s) red[m] += red[m + s];
        __syncthreads();
    }
    if (m == 0) {
        atomicAdd(&out[OFF_PERP], expf(-red[0]));
        if (n == 0) {
            out[OFF_LOSS] = (float)(0.25 * g_loss * (1.0 / 8388608.0));
            g_loss = 0.0;                   // reset for next replay
        }
    }
}

// ---------------- launch ----------------
extern "C" void kernel_launch(void* const* d_in, const int* in_sizes, int n_in,
                              void* d_out, int out_size) {
    const float* x     = (const float*)d_in[0];
    const float* emb   = (const float*)d_in[1];
    const float* ema_c = (const float*)d_in[2];
    const float* ema_w = (const float*)d_in[3];
    float* out = (float*)d_out;

    cudaFuncSetAttribute(vq_main, cudaFuncAttributeMaxDynamicSharedMemorySize, SMEM_BYTES);

    vq_main<<<dim3(T_POS / 128, N_CB), 256, SMEM_BYTES>>>(x, emb, out);
    vq_fin<<<N_CB, M_CODES>>>(ema_c, ema_w, out);
}

// round 15
// speedup vs baseline: 5.4968x; 1.1937x over previous
#include <cuda_runtime.h>
#include <cstdint>

// ---------------- problem constants ----------------
#define N_CB 4
#define M_CODES 512
#define D_DIM 32
#define T_POS 65536

// output layout (float32, reference tuple order, flattened+concatenated)
#define OFF_ZQ   0ULL
#define OFF_LOSS 8388608ULL
#define OFF_PERP 8388609ULL
#define OFF_IDX  8388610ULL
#define OFF_EMB  8650754ULL
#define OFF_CNT  8716290ULL
#define OFF_W    8718338ULL

// fragment-permuted slot: d = kt*8 + 4*h + q4  ->  slot = q4*8 + kt*2 + h
#define SLOT(d) (((d) & 3) * 8 + ((d) >> 3) * 2 + (((d) >> 2) & 1))

// ---------------- smem layout (float offsets), stride 36 rows ----------------
#define SXP_F   0        // x  [128 pos][36]  (permuted)   4608
#define SE_F    4608     // e  [512 code][36] (permuted)  18432
#define SESQ_F  23040    // esq[512]
#define SXSQ_F  23552    // xsq[128]
#define SSAB_F  23680    // sum|x| [128]
#define SBEST_F 23808    // u64[128] packed (dist,code)
#define SFL_F   24064    // flag list u32[128]
#define SWS_F   24192    // warp loss partials [8]
#define SMEM_FLOATS 24200
#define SMEM_BYTES (SMEM_FLOATS * 4)   // 96800 -> 2 CTAs/SM

#define FLT_BIG 3.402823466e38f
#define MARG_COEF 1.6e-4f
#define MARG_ABS  5e-5f
#define FCAP 128

// ---------------- scratch (zero at load; finalize kernels re-zero after use) ----------------
__device__ int    g_counts[N_CB * M_CODES];
__device__ float4 g_dw4[N_CB * M_CODES * 8];
__device__ double g_loss;
__device__ float  g_clap[N_CB * M_CODES];

// ---------------- kernel 1: single-sweep tf32 mma (split chains), top-2, exact recheck ----------------
__global__ void __launch_bounds__(256) vq_main(const float* __restrict__ x,
                                               const float* __restrict__ emb,
                                               float* __restrict__ out) {
    extern __shared__ float sm[];
    __shared__ int fn;
    float* sX   = sm + SXP_F;
    float* sE   = sm + SE_F;
    float* sEsq = sm + SESQ_F;
    float* sXsq = sm + SXSQ_F;
    float* sSab = sm + SSAB_F;
    unsigned long long* sBest = (unsigned long long*)(sm + SBEST_F);
    unsigned int* sFl = (unsigned int*)(sm + SFL_F);
    float* sWs  = sm + SWS_F;

    const int n    = blockIdx.y;
    const int tile = blockIdx.x;
    const int tid  = threadIdx.x;
    const int w    = tid >> 5;
    const int lane = tid & 31;
    const int g    = lane >> 2;
    const int q4   = lane & 3;

    // out[OFF_PERP] must be zero before vq_fin_a accumulates into it
    if (tile == 0 && n == 0 && tid == 0) out[OFF_PERP] = 0.0f;

    // ---- fill x tile (permuted layout) ----
    for (int i = tid; i < 128 * D_DIM; i += 256) {
        int d = i >> 7, p = i & 127;
        int t = tile * 128 + p;
        sX[p * 36 + SLOT(d)] = x[(size_t)(t >> 6) * 8192 + (size_t)n * 2048 + d * 64 + (t & 63)];
    }
    // ---- fill codebook (permuted layout) ----
    const float* en = emb + (size_t)n * M_CODES * D_DIM;
    for (int i = tid; i < M_CODES * D_DIM; i += 256) {
        int m = i >> 5, d = i & 31;
        sE[m * 36 + SLOT(d)] = en[i];
    }
    if (tid == 0) fn = 0;
    __syncthreads();

    // ---- esq: ascending-d fmaf chain (reference-matching) ----
    for (int c = tid; c < M_CODES; c += 256) {
        const float* er = sE + c * 36;
        float s = 0.0f;
#pragma unroll
        for (int d = 0; d < D_DIM; d++) {
            float v = er[SLOT(d)];
            s = fmaf(v, v, s);
        }
        sEsq[c] = s;
    }
    // ---- xsq + sum|x| + sBest init ----
    if (tid < 128) {
        const float* xr = sX + tid * 36;
        float s = 0.0f, a = 0.0f;
#pragma unroll
        for (int d = 0; d < D_DIM; d++) {
            float v = xr[SLOT(d)];
            s = fmaf(v, v, s);
            a += fabsf(v);
        }
        sXsq[tid] = s;
        sSab[tid] = a;
        sBest[tid] = 0xFFFFFFFFFFFFFFFFull;
    }
    __syncthreads();

    // ---- A fragments (4 x LDS.128 per thread) ----
    const int r0 = w * 16 + g;
    const int r1 = r0 + 8;
    float4 xa0 = *(const float4*)&sX[r0 * 36 + q4 * 8];
    float4 xa1 = *(const float4*)&sX[r0 * 36 + q4 * 8 + 4];
    float4 xb0 = *(const float4*)&sX[r1 * 36 + q4 * 8];
    float4 xb1 = *(const float4*)&sX[r1 * 36 + q4 * 8 + 4];
    float af0[4], af1[4], af2[4], af3[4];
    af0[0] = xa0.x; af2[0] = xa0.y; af0[1] = xa0.z; af2[1] = xa0.w;
    af0[2] = xa1.x; af2[2] = xa1.y; af0[3] = xa1.z; af2[3] = xa1.w;
    af1[0] = xb0.x; af3[0] = xb0.y; af1[1] = xb0.z; af3[1] = xb0.w;
    af1[2] = xb1.x; af3[2] = xb1.y; af1[3] = xb1.z; af3[3] = xb1.w;

    const float* peB = sE + g * 36 + q4 * 8;   // advances 288 per nt

    // ---- single branchless sweep: split accumulator chains ----
    float m1_0 = FLT_BIG, m2_0 = FLT_BIG, m1_1 = FLT_BIG, m2_1 = FLT_BIG;
    int   i1_0 = 0, i1_1 = 0;

#pragma unroll 4
    for (int nt = 0; nt < 64; nt++) {
        float a0 = 0.0f, a1 = 0.0f, a2 = 0.0f, a3 = 0.0f;
        float b0 = 0.0f, b1 = 0.0f, b2 = 0.0f, b3 = 0.0f;
        {
            float4 e0 = *(const float4*)(peB + nt * 288);
            float4 e1 = *(const float4*)(peB + nt * 288 + 4);
            float bbf[8] = {e0.x, e0.y, e0.z, e0.w, e1.x, e1.y, e1.z, e1.w};
#pragma unroll
            for (int kt = 0; kt < 2; kt++) {
                asm volatile(
                    "mma.sync.aligned.m16n8k8.row.col.f32.tf32.tf32.f32 "
                    "{%0,%1,%2,%3}, {%4,%5,%6,%7}, {%8,%9}, {%0,%1,%2,%3};"
                    : "+f"(a0), "+f"(a1), "+f"(a2), "+f"(a3)
                    : "f"(af0[kt]), "f"(af1[kt]), "f"(af2[kt]), "f"(af3[kt]),
                      "f"(bbf[2 * kt]), "f"(bbf[2 * kt + 1]));
            }
#pragma unroll
            for (int kt = 2; kt < 4; kt++) {
                asm volatile(
                    "mma.sync.aligned.m16n8k8.row.col.f32.tf32.tf32.f32 "
                    "{%0,%1,%2,%3}, {%4,%5,%6,%7}, {%8,%9}, {%0,%1,%2,%3};"
                    : "+f"(b0), "+f"(b1), "+f"(b2), "+f"(b3)
                    : "f"(af0[kt]), "f"(af1[kt]), "f"(af2[kt]), "f"(af3[kt]),
                      "f"(bbf[2 * kt]), "f"(bbf[2 * kt + 1]));
            }
        }
        float c0 = a0 + b0, c1 = a1 + b1, c2 = a2 + b2, c3 = a3 + b3;

        const int col0 = nt * 8 + q4 * 2;
        float2 e2 = *(const float2*)&sEsq[col0];
        float d00 = fmaf(c0, -2.0f, e2.x);
        float d01 = fmaf(c1, -2.0f, e2.y);
        float d10 = fmaf(c2, -2.0f, e2.x);
        float d11 = fmaf(c3, -2.0f, e2.y);

        {   // row 0: branchless top-2 + index of min
            float lo = fminf(d00, d01);
            float hi = fmaxf(d00, d01);
            int  ilo = (d01 < d00) ? (col0 + 1) : col0;
            m2_0 = fminf(m2_0, fminf(hi, fmaxf(lo, m1_0)));
            i1_0 = (lo < m1_0) ? ilo : i1_0;
            m1_0 = fminf(m1_0, lo);
        }
        {   // row 1
            float lo = fminf(d10, d11);
            float hi = fmaxf(d10, d11);
            int  ilo = (d11 < d10) ? (col0 + 1) : col0;
            m2_1 = fminf(m2_1, fminf(hi, fmaxf(lo, m1_1)));
            i1_1 = (lo < m1_1) ? ilo : i1_1;
            m1_1 = fminf(m1_1, lo);
        }
    }

    const float lm1_0 = m1_0, lm2_0 = m2_0, lm1_1 = m1_1, lm2_1 = m2_1;
    const int   li1_0 = i1_0, li1_1 = i1_1;

    // ---- merge across the 4 quad-threads of each row ----
#pragma unroll
    for (int o = 1; o <= 2; o <<= 1) {
        float om1 = __shfl_xor_sync(0xFFFFFFFFu, m1_0, o);
        float om2 = __shfl_xor_sync(0xFFFFFFFFu, m2_0, o);
        m2_0 = fminf(fminf(m2_0, om2), fmaxf(m1_0, om1));
        m1_0 = fminf(m1_0, om1);
        float pm1 = __shfl_xor_sync(0xFFFFFFFFu, m1_1, o);
        float pm2 = __shfl_xor_sync(0xFFFFFFFFu, m2_1, o);
        m2_1 = fminf(fminf(m2_1, pm2), fmaxf(m1_1, pm1));
        m1_1 = fminf(m1_1, pm1);
    }
    const float thr0 = m1_0 + fmaf(sSab[r0], MARG_COEF, MARG_ABS);
    const float thr1 = m1_1 + fmaf(sSab[r1], MARG_COEF, MARG_ABS);

    // ---- exact fp32 recheck of per-thread minima; flag ranges with 2nd-in-margin ----
#define EXACT_CHECK(row, code) {                                                  \
        const float* xr = sX + (row) * 36;                                        \
        const float* er = sE + (code) * 36;                                       \
        float dot = 0.0f;                                                         \
        _Pragma("unroll")                                                         \
        for (int d = 0; d < D_DIM; d++)                                           \
            dot = fmaf(xr[SLOT(d)], er[SLOT(d)], dot);                            \
        float dist = fmaf(dot, -2.0f, sXsq[row] + sEsq[code]);                    \
        unsigned long long pk = ((unsigned long long)__float_as_uint(dist) << 32) \
                                | (unsigned int)(code);                           \
        atomicMin(&sBest[row], pk);                                               \
    }

    if (lm1_0 <= thr0) EXACT_CHECK(r0, li1_0)
    if (lm1_1 <= thr1) EXACT_CHECK(r1, li1_1)
    if (lm2_0 <= thr0) { int s = atomicAdd(&fn, 1); if (s < FCAP) sFl[s] = (r0 << 2) | q4; }
    if (lm2_1 <= thr1) { int s = atomicAdd(&fn, 1); if (s < FCAP) sFl[s] = (r1 << 2) | q4; }
    __syncthreads();

    // ---- cooperative exact rescan of flagged (row, quad) 128-code ranges ----
    {
        const int nf = (fn < FCAP) ? fn : FCAP;
        for (int i = tid; i < nf * 128; i += 256) {
            const int e = i >> 7, k = i & 127;
            const unsigned int fl = sFl[e];
            const int row = fl >> 2, q = fl & 3;
            const int code = (k >> 1) * 8 + q * 2 + (k & 1);
            EXACT_CHECK(row, code)
        }
        if (fn > FCAP) {   // overflow fallback (practically never)
            for (int i = tid; i < 128 * M_CODES; i += 256) {
                EXACT_CHECK(i >> 9, i & 511)
            }
        }
    }
#undef EXACT_CHECK
    __syncthreads();

    // ---- epilogue: outputs per position ----
    float lloss = 0.0f;
    if (tid < 128) {
        const int pp = tid;
        const int bi = (int)(sBest[pp] & 0xFFFFFFFFull);

        const int t = tile * 128 + pp;
        const int b = t >> 6, l = t & 63;
        out[OFF_IDX + (size_t)b * 256 + (size_t)n * 64 + l] = (float)bi;
        atomicAdd(&g_counts[n * M_CODES + bi], 1);

        float4* dwp = g_dw4 + ((size_t)n * M_CODES + bi) * 8;
        float*  zq  = out + OFF_ZQ + (size_t)b * 8192 + (size_t)n * 2048 + l;
        const float* xr = sX + pp * 36;
        const float* er = sE + bi * 36;
#pragma unroll
        for (int d4 = 0; d4 < 8; d4++) {
            float xv0 = xr[SLOT(d4 * 4 + 0)], q0 = er[SLOT(d4 * 4 + 0)];
            float xv1 = xr[SLOT(d4 * 4 + 1)], q1 = er[SLOT(d4 * 4 + 1)];
            float xv2 = xr[SLOT(d4 * 4 + 2)], q2 = er[SLOT(d4 * 4 + 2)];
            float xv3 = xr[SLOT(d4 * 4 + 3)], q3 = er[SLOT(d4 * 4 + 3)];
            zq[(d4 * 4 + 0) * 64] = __fsub_rn(__fadd_rn(q0, xv0), xv0);
            zq[(d4 * 4 + 1) * 64] = __fsub_rn(__fadd_rn(q1, xv1), xv1);
            zq[(d4 * 4 + 2) * 64] = __fsub_rn(__fadd_rn(q2, xv2), xv2);
            zq[(d4 * 4 + 3) * 64] = __fsub_rn(__fadd_rn(q3, xv3), xv3);
            float f0 = xv0 - q0, f1 = xv1 - q1, f2 = xv2 - q2, f3 = xv3 - q3;
            lloss = fmaf(f0, f0, lloss);
            lloss = fmaf(f1, f1, lloss);
            lloss = fmaf(f2, f2, lloss);
            lloss = fmaf(f3, f3, lloss);
            atomicAdd(dwp + d4, make_float4(xv0, xv1, xv2, xv3));
        }
    }

    // ---- CTA loss reduction -> one double atomic ----
#pragma unroll
    for (int o = 16; o > 0; o >>= 1) lloss += __shfl_down_sync(0xFFFFFFFFu, lloss, o);
    if (lane == 0) sWs[w] = lloss;
    __syncthreads();
    if (tid == 0) {
        double s = 0.0;
#pragma unroll
        for (int ww = 0; ww < 8; ww++) s += (double)sWs[ww];
        atomicAdd(&g_loss, s);
    }
}

// ---------------- kernel 2a: counts -> EMA count, Laplace, perplexity, loss ----------------
__global__ void vq_fin_a(const float* __restrict__ ema_c,
                         float* __restrict__ out) {
    const int n = blockIdx.x;
    const int m = threadIdx.x;
    __shared__ float red[M_CODES];

    const float DECAY = 0.999f;
    const float OMD   = (float)(1.0 - 0.999);
    const float MEPS  = (float)(512.0 * 1e-5);

    const int ci = n * M_CODES + m;
    float cnt  = (float)g_counts[ci];
    g_counts[ci] = 0;                       // reset for next replay
    float cnew = DECAY * ema_c[ci] + OMD * cnt;

    red[m] = cnew;
    __syncthreads();
    for (int s = 256; s > 0; s >>= 1) {
        if (m < s) red[m] += red[m + s];
        __syncthreads();
    }
    float ntot = red[0];
    __syncthreads();

    float clap = (cnew + 1e-5f) / (ntot + MEPS) * ntot;
    out[OFF_CNT + (size_t)ci] = clap;
    g_clap[ci] = clap;

    float p    = cnt * (1.0f / 65536.0f);
    float term = p * logf(p + 1e-10f);
    red[m] = term;
    __syncthreads();
    for (int s = 256; s > 0; s >>= 1) {
        if (m < s) red[m] += red[m + s];
        __syncthreads();
    }
    if (m == 0) {
        atomicAdd(&out[OFF_PERP], expf(-red[0]));
        if (n == 0) {
            out[OFF_LOSS] = (float)(0.25 * g_loss * (1.0 / 8388608.0));
            g_loss = 0.0;                   // reset for next replay
        }
    }
}

// ---------------- kernel 2b: coalesced weight/embedding update (chip-wide) ----------------
__global__ void vq_fin_b(const float* __restrict__ ema_w,
                         float* __restrict__ out) {
    const float DECAY = 0.999f;
    const float OMD   = (float)(1.0 - 0.999);
    float* g_dwf = (float*)g_dw4;

    const int i = blockIdx.x * 512 + threadIdx.x;   // 128 CTAs x 512 = 65536 elements
    float wv = DECAY * ema_w[i] + OMD * g_dwf[i];
    g_dwf[i] = 0.0f;                        // reset for next replay
    out[OFF_W + (size_t)i]   = wv;
    out[OFF_EMB + (size_t)i] = wv / g_clap[i >> 5];
}

// ---------------- launch ----------------
extern "C" void kernel_launch(void* const* d_in, const int* in_sizes, int n_in,
                              void* d_out, int out_size) {
    const float* x     = (const float*)d_in[0];
    const float* emb   = (const float*)d_in[1];
    const float* ema_c = (const float*)d_in[2];
    const float* ema_w = (const float*)d_in[3];
    float* out = (float*)d_out;

    cudaFuncSetAttribute(vq_main, cudaFuncAttributeMaxDynamicSharedMemorySize, SMEM_BYTES);

    vq_main<<<dim3(T_POS / 128, N_CB), 256, SMEM_BYTES>>>(x, emb, out);
    vq_fin_a<<<N_CB, M_CODES>>>(ema_c, out);
    vq_fin_b<<<128, 512>>>(ema_w, out);
}